// round 13
// baseline (speedup 1.0000x reference)
#include <cuda_runtime.h>
#include <cuda_fp16.h>
#include <math.h>
#include <stdint.h>

#define NMAX 100000
#define EMAX 1600000
#define F 128
#define HEADP 108
#define SCHUNK 512
#define NBLK ((NMAX + 127) / 128)

// ---------------- scratch (static device globals; no allocation allowed) ---
__device__ __half2 g_hh[(size_t)NMAX * 64];   // GEMM output (fp16) / gather src
__device__ uint2 g_af[(size_t)NBLK * 8192];   // agg output as A-fragment image
__device__ float g_dinv[NMAX];
__device__ int   g_deg[NMAX];
__device__ int   g_rowptr[NMAX + 1];
__device__ int   g_fill[NMAX];
__device__ int   g_src[EMAX];                 // CSR (by destination) source ids
__device__ int   g_bsum[256];
__device__ float g_hb[HEADP];
__device__ int   g_is64;
// W fragment images (fp16 hi/lo): [8 k16-steps][16 ntiles][2 regs][32 lanes]
__device__ uint2 g_bw[8192];                  // mainline layer weights
__device__ uint2 g_bw2[8192];                 // packed head weights

#define MMA_F16(cc, a, b)                                                      \
    asm volatile(                                                              \
        "mma.sync.aligned.m16n8k16.row.col.f32.f16.f16.f32 "                   \
        "{%0,%1,%2,%3},{%4,%5,%6,%7},{%8,%9},{%0,%1,%2,%3};"                   \
        : "+f"((cc)[0]), "+f"((cc)[1]), "+f"((cc)[2]), "+f"((cc)[3])           \
        : "r"((a)[0]), "r"((a)[1]), "r"((a)[2]), "r"((a)[3]),                  \
          "r"((b)[0]), "r"((b)[1]))

// load 4 consecutive h cols (2 half2) and widen to float4
__device__ __forceinline__ float4 ldh4(const __half2* p) {
    uint2 u = __ldg((const uint2*)p);
    __half2 h0 = *(__half2*)&u.x;
    __half2 h1 = *(__half2*)&u.y;
    float2 f0 = __half22float2(h0);
    float2 f1 = __half22float2(h1);
    return make_float4(f0.x, f0.y, f1.x, f1.y);
}

// split a float pair into packed fp16 (hi, lo residual)
__device__ __forceinline__ uint2 h2split(float v0, float v1) {
    __half2 hi2 = __floats2half2_rn(v0, v1);
    float2 hf = __half22float2(hi2);
    __half2 lo2 = __floats2half2_rn(v0 - hf.x, v1 - hf.y);
    uint2 r;
    r.x = *(unsigned*)&hi2;
    r.y = *(unsigned*)&lo2;
    return r;
}

// ---------------- detect dtype + zero degrees (fused) ----------------------
__global__ void zdetect_kernel(const int* __restrict__ e, int n) {
    int i = blockIdx.x * blockDim.x + threadIdx.x;
    if (i < n) g_deg[i] = 0;
    if (blockIdx.x == 0 && threadIdx.x < 32) {
        int l = threadIdx.x;
        int bad = 0;
        for (int j = l; j < 256; j += 32)
            if (e[2 * j + 1] != 0) bad = 1;
        unsigned b = __ballot_sync(0xffffffffu, bad);
        if (l == 0) g_is64 = (b == 0) ? 1 : 0;
    }
}

__device__ __forceinline__ int ldidx(const void* p, long long i, int is64) {
    return is64 ? (int)((const long long*)p)[i] : ((const int*)p)[i];
}

// ---------------- count degrees (direct edge_index read) --------------------
__global__ void count_kernel(const void* __restrict__ eidx, long long E) {
    long long t = (long long)blockIdx.x * blockDim.x + threadIdx.x;
    if (t >= E) return;
    atomicAdd(&g_deg[ldidx(eidx, E + t, g_is64)], 1);
}

// ---------------- hierarchical scan (2 stages) ------------------------------
__global__ void scan1_kernel(int n) {
    __shared__ int sh[SCHUNK];
    int t = threadIdx.x;
    int i = blockIdx.x * SCHUNK + t;
    sh[t] = (i < n) ? g_deg[i] : 0;
    __syncthreads();
#pragma unroll
    for (int off = SCHUNK / 2; off; off >>= 1) {
        if (t < off) sh[t] += sh[t + off];
        __syncthreads();
    }
    if (t == 0) g_bsum[blockIdx.x] = sh[0];
}

__global__ void scan3_kernel(int n, int nb) {
    __shared__ int bs[256];
    __shared__ int sh[SCHUNK];
    int t = threadIdx.x;
    if (t < 256) bs[t] = (t < nb) ? g_bsum[t] : 0;
    __syncthreads();
#pragma unroll
    for (int off = 1; off < 256; off <<= 1) {
        int u = (t < 256 && t >= off) ? bs[t - off] : 0;
        __syncthreads();
        if (t < 256) bs[t] += u;
        __syncthreads();
    }
    int boff = (blockIdx.x == 0) ? 0 : bs[blockIdx.x - 1];
    if (blockIdx.x == 0 && t == 0) g_rowptr[n] = bs[nb - 1];

    int i = blockIdx.x * SCHUNK + t;
    int d = (i < n) ? g_deg[i] : 0;
    sh[t] = d;
    __syncthreads();
#pragma unroll
    for (int off = 1; off < SCHUNK; off <<= 1) {
        int u = (t >= off) ? sh[t - off] : 0;
        __syncthreads();
        sh[t] += u;
        __syncthreads();
    }
    if (i < n) {
        int pre = boff + sh[t] - d;
        g_rowptr[i] = pre;
        g_fill[i]   = pre;
        g_dinv[i]   = rsqrtf((float)(d + 1));  // +1 self-loop
    }
}

__global__ void fill_kernel(const void* __restrict__ eidx, long long E) {
    long long e = (long long)blockIdx.x * blockDim.x + threadIdx.x;
    if (e >= E) return;
    int is64 = g_is64;
    int r = ldidx(eidx, e, is64);
    int c = ldidx(eidx, E + e, is64);
    int pos = atomicAdd(&g_fill[c], 1);
    g_src[pos] = r;
}

// ---------------- W prep: fp16 hi/lo split into m16n8k16 B-fragment image ---
__global__ void prep_w_kernel(const float* __restrict__ W, uint2* __restrict__ img) {
    int p = blockIdx.x * blockDim.x + threadIdx.x;
    if (p >= 8192) return;
    int kp = p >> 7, n = p & 127;
    int k = 2 * kp;
    float v0 = W[k * 128 + n];
    float v1 = W[(k + 1) * 128 + n];
    int s = k >> 4, kw = k & 15;
    int reg = kw >> 3, t = (kw & 7) >> 1;
    int tile = s * 16 + (n >> 3);
    img[(tile * 2 + reg) * 32 + (n & 7) * 4 + t] = h2split(v0, v1);
}

// same, gathering packed head weights (cls|sim|hom|ent, zero-padded to 128)
__global__ void prep_head_kernel(const float* __restrict__ cls_w,
                                 const float* __restrict__ cls_b,
                                 const float* __restrict__ sim_w,
                                 const float* __restrict__ sim_b,
                                 const float* __restrict__ hom_w,
                                 const float* __restrict__ hom_b,
                                 const float* __restrict__ ent_w,
                                 const float* __restrict__ ent_b) {
    int p = blockIdx.x * blockDim.x + threadIdx.x;
    if (p < HEADP) {
        float v = 0.f;
        if (p < 64)        v = cls_b[p];
        else if (p < 104)  v = sim_b[p - 64];
        else if (p == 104) v = hom_b[0];
        else if (p == 105) v = ent_b[0];
        g_hb[p] = v;
    }
    if (p >= 8192) return;
    int kp = p >> 7, n = p & 127;
    int k = 2 * kp;
    float v0 = 0.f, v1 = 0.f;
    if (n < 64)        { v0 = cls_w[k * 64 + n];        v1 = cls_w[(k + 1) * 64 + n]; }
    else if (n < 104)  { v0 = sim_w[k * 40 + n - 64];   v1 = sim_w[(k + 1) * 40 + n - 64]; }
    else if (n == 104) { v0 = hom_w[k];                 v1 = hom_w[k + 1]; }
    else if (n == 105) { v0 = ent_w[k];                 v1 = ent_w[k + 1]; }
    int s = k >> 4, kw = k & 15;
    int reg = kw >> 3, t = (kw & 7) >> 1;
    int tile = s * 16 + (n >> 3);
    g_bw2[(tile * 2 + reg) * 32 + (n & 7) * 4 + t] = h2split(v0, v1);
}

// ---------------- fp16 mma compute core (hh + hl + lh) ----------------------
// Block: 128x128, 8 warps (2M x 4N), warp tile 64x32, 8 k16-steps.
// As layout: [mtile(8)][s(8)][reg(4)][lane(32)] uint2.
__device__ __forceinline__ void mma_compute(const uint2* __restrict__ bimg,
                                            const uint2* As,
                                            int lane, int wm, int wn,
                                            float c[4][4][4]) {
#pragma unroll
    for (int s = 0; s < 8; s++) {
        unsigned bh[4][2], bl[4][2];
#pragma unroll
        for (int nf = 0; nf < 4; nf++)
#pragma unroll
            for (int rg = 0; rg < 2; rg++) {
                uint2 b = __ldg(&bimg[((s * 16 + wn * 4 + nf) * 2 + rg) * 32 + lane]);
                bh[nf][rg] = b.x;
                bl[nf][rg] = b.y;
            }
#pragma unroll
        for (int mf = 0; mf < 4; mf++) {
            unsigned ah[4], al[4];
            int mtile = wm * 4 + mf;
#pragma unroll
            for (int rg = 0; rg < 4; rg++) {
                uint2 a = As[((mtile * 8 + s) * 4 + rg) * 32 + lane];
                ah[rg] = a.x;
                al[rg] = a.y;
            }
#pragma unroll
            for (int nf = 0; nf < 4; nf++) {
                MMA_F16(c[mf][nf], ah, bh[nf]);
                MMA_F16(c[mf][nf], ah, bl[nf]);
                MMA_F16(c[mf][nf], al, bh[nf]);
            }
        }
    }
}

// stage A by splitting fp32 source (layer 1 only)
__device__ __forceinline__ void stage_split(const float* __restrict__ A,
                                            uint2* As, long long row0, int M,
                                            int tid) {
    for (int idx = tid; idx < 4096; idx += 256) {
        int r = idx >> 5, q = idx & 31;
        long long gr = row0 + r;
        float4 v = make_float4(0.f, 0.f, 0.f, 0.f);
        if (gr < M) v = __ldg((const float4*)(A + gr * F) + q);
        int mtile = r >> 4, ri = r & 15;
        int g = ri & 7, rowhalf = ri >> 3;
        float vals[4] = {v.x, v.y, v.z, v.w};
#pragma unroll
        for (int j = 0; j < 2; j++) {
            int kk = 4 * q + 2 * j;
            int s = kk >> 4, kw = kk & 15;
            int reg = (kw >> 3) * 2 + rowhalf;
            int t = (kw & 7) >> 1;
            As[((mtile * 8 + s) * 4 + reg) * 32 + g * 4 + t] =
                h2split(vals[2 * j], vals[2 * j + 1]);
        }
    }
    __syncthreads();
}

// stage A by pure copy of the prebuilt fragment image (layer 2 / head)
// 64KB tile = 4096 uint4 (16 per thread), fully coalesced.
__device__ __forceinline__ void stage_copy(const uint2* __restrict__ AF,
                                           uint2* As, int blk, int tid) {
    const uint4* src = (const uint4*)(AF + (size_t)blk * 8192);
    uint4* dst = (uint4*)As;
    for (int i = tid; i < 4096; i += 256) dst[i] = __ldg(&src[i]);
    __syncthreads();
}

// ---------------- layer-1 GEMM: h[M,128] = x[M,128] @ W1 (fp16 out) ---------
__global__ __launch_bounds__(256, 2)
void tgemm_kernel(const float* __restrict__ A, int M) {
    extern __shared__ uint2 smu[];
    uint2* As = smu;          // 64KB

    int tid = threadIdx.x, lane = tid & 31, wid = tid >> 5;
    int wm = wid >> 2, wn = wid & 3;
    long long row0 = (long long)blockIdx.x * 128;

    float c[4][4][4];
#pragma unroll
    for (int a = 0; a < 4; a++)
#pragma unroll
        for (int b = 0; b < 4; b++)
#pragma unroll
            for (int d = 0; d < 4; d++) c[a][b][d] = 0.f;

    stage_split(A, As, row0, M, tid);
    mma_compute(g_bw, As, lane, wm, wn, c);

#pragma unroll
    for (int mf = 0; mf < 4; mf++) {
        long long r0 = row0 + wm * 64 + mf * 16 + (lane >> 2);
#pragma unroll
        for (int nf = 0; nf < 4; nf++) {
            int ch = wn * 16 + nf * 4 + (lane & 3);   // half2 column index
            if (r0 < M)
                g_hh[r0 * 64 + ch] = __floats2half2_rn(c[mf][nf][0], c[mf][nf][1]);
            if (r0 + 8 < M)
                g_hh[(r0 + 8) * 64 + ch] = __floats2half2_rn(c[mf][nf][2], c[mf][nf][3]);
        }
    }
}

// ---------------- layer-2 GEMM: h = af @ W (copy staging, fp16 out) ---------
__global__ __launch_bounds__(256, 2)
void tgemm2_kernel(int M) {
    extern __shared__ uint2 smu[];
    uint2* As = smu;

    int tid = threadIdx.x, lane = tid & 31, wid = tid >> 5;
    int wm = wid >> 2, wn = wid & 3;
    long long row0 = (long long)blockIdx.x * 128;

    float c[4][4][4];
#pragma unroll
    for (int a = 0; a < 4; a++)
#pragma unroll
        for (int b = 0; b < 4; b++)
#pragma unroll
            for (int d = 0; d < 4; d++) c[a][b][d] = 0.f;

    stage_copy(g_af, As, blockIdx.x, tid);
    mma_compute(g_bw, As, lane, wm, wn, c);

#pragma unroll
    for (int mf = 0; mf < 4; mf++) {
        long long r0 = row0 + wm * 64 + mf * 16 + (lane >> 2);
#pragma unroll
        for (int nf = 0; nf < 4; nf++) {
            int ch = wn * 16 + nf * 4 + (lane & 3);
            if (r0 < M)
                g_hh[r0 * 64 + ch] = __floats2half2_rn(c[mf][nf][0], c[mf][nf][1]);
            if (r0 + 8 < M)
                g_hh[(r0 + 8) * 64 + ch] = __floats2half2_rn(c[mf][nf][2], c[mf][nf][3]);
        }
    }
}

// ---------------- head GEMM (copy staging) + fused finisher ------------------
__global__ __launch_bounds__(256, 2)
void head_mma_kernel(float* __restrict__ out, int M) {
    extern __shared__ uint2 smu[];
    uint2* As = smu;               // 64KB
    float* Cs = (float*)smu;       // reused after mainloop: 128 x 128 floats
    __shared__ float sbias[128];

    int tid = threadIdx.x, lane = tid & 31, wid = tid >> 5;
    int wm = wid >> 2, wn = wid & 3;
    long long row0 = (long long)blockIdx.x * 128;

    if (tid < 128) sbias[tid] = (tid < HEADP) ? g_hb[tid] : 0.f;

    float c[4][4][4];
#pragma unroll
    for (int a = 0; a < 4; a++)
#pragma unroll
        for (int b = 0; b < 4; b++)
#pragma unroll
            for (int d = 0; d < 4; d++) c[a][b][d] = 0.f;

    stage_copy(g_af, As, blockIdx.x, tid);
    mma_compute(g_bw2, As, lane, wm, wn, c);
    __syncthreads();   // all warps done reading As before Cs overwrite

    // stage C into SMEM (stride 128 -> finisher reads are conflict-free)
#pragma unroll
    for (int mf = 0; mf < 4; mf++) {
        int r0 = wm * 64 + mf * 16 + (lane >> 2);
#pragma unroll
        for (int nf = 0; nf < 4; nf++) {
            int col = wn * 32 + nf * 8 + 2 * (lane & 3);
            *(float2*)&Cs[r0 * 128 + col] = make_float2(c[mf][nf][0], c[mf][nf][1]);
            *(float2*)&Cs[(r0 + 8) * 128 + col] = make_float2(c[mf][nf][2], c[mf][nf][3]);
        }
    }
    __syncthreads();

    float* out_main = out;                     // [M,64]
    float* out_sim  = out + (size_t)M * 64;    // [M,40]
    float* out_hom  = out + (size_t)M * 104;   // [M]
    float* out_ent  = out + (size_t)M * 105;   // [M]

    for (int i = 0; i < 16; i++) {
        int row = wid * 16 + i;
        long long gr = row0 + row;
        if (gr >= M) break;
        const float* g = Cs + row * 128;

        // log_softmax over cols [0,64)
        float a = g[lane] + sbias[lane];
        float b = g[32 + lane] + sbias[32 + lane];
        float m1 = fmaxf(a, b);
#pragma unroll
        for (int o = 16; o; o >>= 1)
            m1 = fmaxf(m1, __shfl_xor_sync(0xffffffffu, m1, o));
        float s = expf(a - m1) + expf(b - m1);
#pragma unroll
        for (int o = 16; o; o >>= 1) s += __shfl_xor_sync(0xffffffffu, s, o);
        float ls = m1 + logf(s);
        out_main[gr * 64 + lane]      = a - ls;
        out_main[gr * 64 + 32 + lane] = b - ls;

        // softmax over cols [64,104)
        float u = g[64 + lane] + sbias[64 + lane];
        float v2 = (lane < 8) ? g[96 + lane] + sbias[96 + lane] : -3.0e38f;
        float m2 = fmaxf(u, v2);
#pragma unroll
        for (int o = 16; o; o >>= 1)
            m2 = fmaxf(m2, __shfl_xor_sync(0xffffffffu, m2, o));
        float e1 = expf(u - m2);
        float e2 = (lane < 8) ? expf(v2 - m2) : 0.f;
        float s2 = e1 + e2;
#pragma unroll
        for (int o = 16; o; o >>= 1) s2 += __shfl_xor_sync(0xffffffffu, s2, o);
        float inv = 1.f / s2;
        out_sim[gr * 40 + lane] = e1 * inv;
        if (lane < 8) out_sim[gr * 40 + 32 + lane] = e2 * inv;

        // sigmoids
        if (lane == 0) out_hom[gr] = 1.f / (1.f + expf(-(g[104] + sbias[104])));
        if (lane == 1) out_ent[gr] = 1.f / (1.f + expf(-(g[105] + sbias[105])));
    }
}

// ---------------- CSR gather aggregation (fp16 src, fragment-image out) -----
// mode 1: +b1, BN(eval), ReLU.   mode 2: +b2.   4-way unrolled gather (MLP=4).
// Output written directly as the m16n8k16 A-fragment image consumed by
// tgemm2 / head_mma (hi/lo fp16 split, 8B per 4 cols == fp32 volume).
__global__ void agg_kernel(int n, int mode,
                           const float* __restrict__ bias,
                           const float* __restrict__ gamma,
                           const float* __restrict__ beta,
                           const float* __restrict__ mean,
                           const float* __restrict__ var) {
    int node = blockIdx.x * (blockDim.x >> 5) + (threadIdx.x >> 5);
    if (node >= n) return;
    int l = threadIdx.x & 31;

    float d = g_dinv[node];

    float4 a0 = ldh4(g_hh + (size_t)node * 64 + 2 * l);
    float d2 = d * d;
    a0.x *= d2; a0.y *= d2; a0.z *= d2; a0.w *= d2;
    float4 a1 = make_float4(0.f, 0.f, 0.f, 0.f);
    float4 a2 = make_float4(0.f, 0.f, 0.f, 0.f);
    float4 a3 = make_float4(0.f, 0.f, 0.f, 0.f);

    int s = g_rowptr[node], e2 = g_rowptr[node + 1];
    for (int base = s; base < e2; base += 32) {
        int idx = base + l;
        int r = (idx < e2) ? g_src[idx] : 0;
        float dr = (idx < e2) ? g_dinv[r] * d : 0.f;
        int m = e2 - base; if (m > 32) m = 32;
        int j = 0;
        for (; j + 4 <= m; j += 4) {
            int r0 = __shfl_sync(0xffffffffu, r, j);
            int r1 = __shfl_sync(0xffffffffu, r, j + 1);
            int r2 = __shfl_sync(0xffffffffu, r, j + 2);
            int r3 = __shfl_sync(0xffffffffu, r, j + 3);
            float n0 = __shfl_sync(0xffffffffu, dr, j);
            float n1 = __shfl_sync(0xffffffffu, dr, j + 1);
            float n2 = __shfl_sync(0xffffffffu, dr, j + 2);
            float n3 = __shfl_sync(0xffffffffu, dr, j + 3);
            float4 v0 = ldh4(g_hh + (size_t)r0 * 64 + 2 * l);
            float4 v1 = ldh4(g_hh + (size_t)r1 * 64 + 2 * l);
            float4 v2 = ldh4(g_hh + (size_t)r2 * 64 + 2 * l);
            float4 v3 = ldh4(g_hh + (size_t)r3 * 64 + 2 * l);
            a0.x += v0.x * n0; a0.y += v0.y * n0; a0.z += v0.z * n0; a0.w += v0.w * n0;
            a1.x += v1.x * n1; a1.y += v1.y * n1; a1.z += v1.z * n1; a1.w += v1.w * n1;
            a2.x += v2.x * n2; a2.y += v2.y * n2; a2.z += v2.z * n2; a2.w += v2.w * n2;
            a3.x += v3.x * n3; a3.y += v3.y * n3; a3.z += v3.z * n3; a3.w += v3.w * n3;
        }
        for (; j < m; j++) {
            int r0 = __shfl_sync(0xffffffffu, r, j);
            float n0 = __shfl_sync(0xffffffffu, dr, j);
            float4 v0 = ldh4(g_hh + (size_t)r0 * 64 + 2 * l);
            a0.x += v0.x * n0; a0.y += v0.y * n0; a0.z += v0.z * n0; a0.w += v0.w * n0;
        }
    }
    a0.x += a1.x + a2.x + a3.x;
    a0.y += a1.y + a2.y + a3.y;
    a0.z += a1.z + a2.z + a3.z;
    a0.w += a1.w + a2.w + a3.w;

    int c0 = 4 * l;
    float outv[4] = {a0.x, a0.y, a0.z, a0.w};
    if (mode == 1) {
#pragma unroll
        for (int m = 0; m < 4; m++) {
            int c = c0 + m;
            float v = outv[m] + bias[c];
            float sc = gamma[c] * rsqrtf(var[c] + 1e-5f);
            v = (v - mean[c]) * sc + beta[c];
            outv[m] = fmaxf(v, 0.f);
        }
    } else {
#pragma unroll
        for (int m = 0; m < 4; m++) outv[m] += bias[c0 + m];
    }

    // write as A-fragment image: node -> (blk, r); lane covers k-pairs c0, c0+2
    int blk = node >> 7, rr = node & 127;
    int mtile = rr >> 4, ri = rr & 15;
    int g = ri & 7, rowhalf = ri >> 3;
    uint2* dst = g_af + (size_t)blk * 8192;
    {
        int kw = c0 & 15, sA = c0 >> 4;
        int reg = (kw >> 3) * 2 + rowhalf, t = (kw & 7) >> 1;
        dst[((mtile * 8 + sA) * 4 + reg) * 32 + g * 4 + t] = h2split(outv[0], outv[1]);
    }
    {
        int kk = c0 + 2;
        int kw = kk & 15, sA = kk >> 4;
        int reg = (kw >> 3) * 2 + rowhalf, t = (kw & 7) >> 1;
        dst[((mtile * 8 + sA) * 4 + reg) * 32 + g * 4 + t] = h2split(outv[2], outv[3]);
    }
}

// ---------------- launch ------------------------------------------------------
extern "C" void kernel_launch(void* const* d_in, const int* in_sizes, int n_in,
                              void* d_out, int out_size) {
    const float* x     = (const float*)d_in[0];
    const void*  eidx  = d_in[1];
    const float* w1    = (const float*)d_in[2];
    const float* b1    = (const float*)d_in[3];
    const float* w2    = (const float*)d_in[4];
    const float* b2    = (const float*)d_in[5];
    const float* gamma = (const float*)d_in[6];
    const float* beta  = (const float*)d_in[7];
    const float* mean  = (const float*)d_in[8];
    const float* var   = (const float*)d_in[9];
    const float* cls_w = (const float*)d_in[10];
    const float* cls_b = (const float*)d_in[11];
    const float* sim_w = (const float*)d_in[12];
    const float* sim_b = (const float*)d_in[13];
    const float* hom_w = (const float*)d_in[14];
    const float* hom_b = (const float*)d_in[15];
    const float* ent_w = (const float*)d_in[16];
    const float* ent_b = (const float*)d_in[17];

    int N = in_sizes[0] / F;
    long long E = (long long)in_sizes[1] / 2;
    float* out = (float*)d_out;

    uint2* p_bw = nullptr;
    cudaGetSymbolAddress((void**)&p_bw, g_bw);

    size_t smemT = 8192 * sizeof(uint2);                  // 64 KB (full A tile)
    cudaFuncSetAttribute(tgemm_kernel, cudaFuncAttributeMaxDynamicSharedMemorySize,
                         (int)smemT);
    cudaFuncSetAttribute(tgemm2_kernel, cudaFuncAttributeMaxDynamicSharedMemorySize,
                         (int)smemT);
    cudaFuncSetAttribute(head_mma_kernel, cudaFuncAttributeMaxDynamicSharedMemorySize,
                         (int)smemT);

    int tb = 256;
    int nscan = (N + SCHUNK - 1) / SCHUNK;
    int tgG = (N + 127) / 128;

    // order chosen so tgemm1 is OUR index 3 == ncu's global launch 5
    prep_w_kernel<<<32, 256>>>(w1, p_bw);                              // 0
    zdetect_kernel<<<(N + tb - 1) / tb, tb>>>((const int*)eidx, N);    // 1
    count_kernel<<<(unsigned)((E + tb - 1) / tb), tb>>>(eidx, E);      // 2
    tgemm_kernel<<<tgG, tb, smemT>>>(x, N);                            // 3 <- ncu
    scan1_kernel<<<nscan, SCHUNK>>>(N);                                // 4
    scan3_kernel<<<nscan, SCHUNK>>>(N, nscan);                         // 5
    fill_kernel<<<(unsigned)((E + tb - 1) / tb), tb>>>(eidx, E);       // 6
    agg_kernel<<<(N + 7) / 8, tb>>>(N, 1, b1, gamma, beta, mean, var); // 7

    // layer 2
    prep_w_kernel<<<32, 256>>>(w2, p_bw);
    tgemm2_kernel<<<tgG, tb, smemT>>>(N);
    agg_kernel<<<(N + 7) / 8, tb>>>(N, 2, b2, nullptr, nullptr, nullptr, nullptr);

    // heads (mma + fused finisher)
    prep_head_kernel<<<32, 256>>>(cls_w, cls_b, sim_w, sim_b,
                                  hom_w, hom_b, ent_w, ent_b);
    head_mma_kernel<<<tgG, tb, smemT>>>(out, N);
}

// round 14
// speedup vs baseline: 1.1268x; 1.1268x over previous
#include <cuda_runtime.h>
#include <cuda_fp16.h>
#include <math.h>
#include <stdint.h>

#define NMAX 100000
#define EMAX 1600000
#define F 128
#define HEADP 108
#define SCHUNK 512

// ---------------- scratch (static device globals; no allocation allowed) ---
__device__ __half2 g_hh[(size_t)NMAX * 64];   // GEMM output (fp16) / gather src
__device__ float g_agg[(size_t)NMAX * F];     // aggregation output (fp32)
__device__ float g_dinv[NMAX];
__device__ int   g_deg[NMAX];
__device__ int   g_rowptr[NMAX + 1];
__device__ int   g_fill[NMAX];
__device__ int   g_src[EMAX];                 // CSR (by destination) source ids
__device__ int   g_bsum[256];
__device__ float g_hb[HEADP];
__device__ int   g_is64;
// W fragment images (fp16 hi/lo): [8 k16-steps][16 ntiles][2 regs][32 lanes]
__device__ uint2 g_bw[8192];                  // mainline layer weights
__device__ uint2 g_bw2[8192];                 // packed head weights

#define MMA_F16(cc, a0, a1, a2, a3, b)                                         \
    asm volatile(                                                              \
        "mma.sync.aligned.m16n8k16.row.col.f32.f16.f16.f32 "                   \
        "{%0,%1,%2,%3},{%4,%5,%6,%7},{%8,%9},{%0,%1,%2,%3};"                   \
        : "+f"((cc)[0]), "+f"((cc)[1]), "+f"((cc)[2]), "+f"((cc)[3])           \
        : "r"(a0), "r"(a1), "r"(a2), "r"(a3),                                  \
          "r"((b)[0]), "r"((b)[1]))

// load 4 consecutive h cols (2 half2) and widen to float4
__device__ __forceinline__ float4 ldh4(const __half2* p) {
    uint2 u = __ldg((const uint2*)p);
    __half2 h0 = *(__half2*)&u.x;
    __half2 h1 = *(__half2*)&u.y;
    float2 f0 = __half22float2(h0);
    float2 f1 = __half22float2(h1);
    return make_float4(f0.x, f0.y, f1.x, f1.y);
}

// split a float pair into packed fp16 (hi, lo residual)
__device__ __forceinline__ uint2 h2split(float v0, float v1) {
    __half2 hi2 = __floats2half2_rn(v0, v1);
    float2 hf = __half22float2(hi2);
    __half2 lo2 = __floats2half2_rn(v0 - hf.x, v1 - hf.y);
    uint2 r;
    r.x = *(unsigned*)&hi2;
    r.y = *(unsigned*)&lo2;
    return r;
}

__device__ __forceinline__ unsigned h2pack(float v0, float v1) {
    __half2 h = __floats2half2_rn(v0, v1);
    return *(unsigned*)&h;
}

// ---------------- detect dtype + zero degrees (fused) ----------------------
__global__ void zdetect_kernel(const int* __restrict__ e, int n) {
    int i = blockIdx.x * blockDim.x + threadIdx.x;
    if (i < n) g_deg[i] = 0;
    if (blockIdx.x == 0 && threadIdx.x < 32) {
        int l = threadIdx.x;
        int bad = 0;
        for (int j = l; j < 256; j += 32)
            if (e[2 * j + 1] != 0) bad = 1;
        unsigned b = __ballot_sync(0xffffffffu, bad);
        if (l == 0) g_is64 = (b == 0) ? 1 : 0;
    }
}

__device__ __forceinline__ int ldidx(const void* p, long long i, int is64) {
    return is64 ? (int)((const long long*)p)[i] : ((const int*)p)[i];
}

// ---------------- count degrees (direct edge_index read) --------------------
__global__ void count_kernel(const void* __restrict__ eidx, long long E) {
    long long t = (long long)blockIdx.x * blockDim.x + threadIdx.x;
    if (t >= E) return;
    atomicAdd(&g_deg[ldidx(eidx, E + t, g_is64)], 1);
}

// ---------------- hierarchical scan (2 stages) ------------------------------
__global__ void scan1_kernel(int n) {
    __shared__ int sh[SCHUNK];
    int t = threadIdx.x;
    int i = blockIdx.x * SCHUNK + t;
    sh[t] = (i < n) ? g_deg[i] : 0;
    __syncthreads();
#pragma unroll
    for (int off = SCHUNK / 2; off; off >>= 1) {
        if (t < off) sh[t] += sh[t + off];
        __syncthreads();
    }
    if (t == 0) g_bsum[blockIdx.x] = sh[0];
}

__global__ void scan3_kernel(int n, int nb) {
    __shared__ int bs[256];
    __shared__ int sh[SCHUNK];
    int t = threadIdx.x;
    if (t < 256) bs[t] = (t < nb) ? g_bsum[t] : 0;
    __syncthreads();
#pragma unroll
    for (int off = 1; off < 256; off <<= 1) {
        int u = (t < 256 && t >= off) ? bs[t - off] : 0;
        __syncthreads();
        if (t < 256) bs[t] += u;
        __syncthreads();
    }
    int boff = (blockIdx.x == 0) ? 0 : bs[blockIdx.x - 1];
    if (blockIdx.x == 0 && t == 0) g_rowptr[n] = bs[nb - 1];

    int i = blockIdx.x * SCHUNK + t;
    int d = (i < n) ? g_deg[i] : 0;
    sh[t] = d;
    __syncthreads();
#pragma unroll
    for (int off = 1; off < SCHUNK; off <<= 1) {
        int u = (t >= off) ? sh[t - off] : 0;
        __syncthreads();
        sh[t] += u;
        __syncthreads();
    }
    if (i < n) {
        int pre = boff + sh[t] - d;
        g_rowptr[i] = pre;
        g_fill[i]   = pre;
        g_dinv[i]   = rsqrtf((float)(d + 1));  // +1 self-loop
    }
}

__global__ void fill_kernel(const void* __restrict__ eidx, long long E) {
    long long e = (long long)blockIdx.x * blockDim.x + threadIdx.x;
    if (e >= E) return;
    int is64 = g_is64;
    int r = ldidx(eidx, e, is64);
    int c = ldidx(eidx, E + e, is64);
    int pos = atomicAdd(&g_fill[c], 1);
    g_src[pos] = r;
}

// ---------------- W prep: fp16 hi/lo split into m16n8k16 B-fragment image ---
__global__ void prep_w_kernel(const float* __restrict__ W, uint2* __restrict__ img) {
    int p = blockIdx.x * blockDim.x + threadIdx.x;
    if (p >= 8192) return;
    int kp = p >> 7, n = p & 127;
    int k = 2 * kp;
    float v0 = W[k * 128 + n];
    float v1 = W[(k + 1) * 128 + n];
    int s = k >> 4, kw = k & 15;
    int reg = kw >> 3, t = (kw & 7) >> 1;
    int tile = s * 16 + (n >> 3);
    img[(tile * 2 + reg) * 32 + (n & 7) * 4 + t] = h2split(v0, v1);
}

// same, gathering packed head weights (cls|sim|hom|ent, zero-padded to 128)
__global__ void prep_head_kernel(const float* __restrict__ cls_w,
                                 const float* __restrict__ cls_b,
                                 const float* __restrict__ sim_w,
                                 const float* __restrict__ sim_b,
                                 const float* __restrict__ hom_w,
                                 const float* __restrict__ hom_b,
                                 const float* __restrict__ ent_w,
                                 const float* __restrict__ ent_b) {
    int p = blockIdx.x * blockDim.x + threadIdx.x;
    if (p < HEADP) {
        float v = 0.f;
        if (p < 64)        v = cls_b[p];
        else if (p < 104)  v = sim_b[p - 64];
        else if (p == 104) v = hom_b[0];
        else if (p == 105) v = ent_b[0];
        g_hb[p] = v;
    }
    if (p >= 8192) return;
    int kp = p >> 7, n = p & 127;
    int k = 2 * kp;
    float v0 = 0.f, v1 = 0.f;
    if (n < 64)        { v0 = cls_w[k * 64 + n];        v1 = cls_w[(k + 1) * 64 + n]; }
    else if (n < 104)  { v0 = sim_w[k * 40 + n - 64];   v1 = sim_w[(k + 1) * 40 + n - 64]; }
    else if (n == 104) { v0 = hom_w[k];                 v1 = hom_w[k + 1]; }
    else if (n == 105) { v0 = ent_w[k];                 v1 = ent_w[k + 1]; }
    int s = k >> 4, kw = k & 15;
    int reg = kw >> 3, t = (kw & 7) >> 1;
    int tile = s * 16 + (n >> 3);
    g_bw2[(tile * 2 + reg) * 32 + (n & 7) * 4 + t] = h2split(v0, v1);
}

// ---------------- fp16 mma mainloop: A single fp16, B 2-term hi/lo ----------
// Block: 128x128, 8 warps (2M x 4N), warp tile 64x32, 8 k16-steps.
// As layout: [mtile(8)][s(8)][lane(32)][reg(4)] unsigned (32KB) -> one
// conflict-free LDS.128 per A fragment. Per (mf,nf,s): 2 MMAs (a*bh, a*bl).
__device__ __forceinline__ void mma_mainloop(const float* __restrict__ A,
                                             const uint2* __restrict__ bimg,
                                             unsigned* As,
                                             long long row0, int M,
                                             int tid, int lane, int wm, int wn,
                                             float c[4][4][4]) {
    // stage ALL of A as plain fp16: 4096 float4 loads block-wide
    for (int idx = tid; idx < 4096; idx += 256) {
        int r = idx >> 5, q = idx & 31;           // row, float4-col
        long long gr = row0 + r;
        float4 v = make_float4(0.f, 0.f, 0.f, 0.f);
        if (gr < M) v = __ldg((const float4*)(A + gr * F) + q);
        int mtile = r >> 4, ri = r & 15;
        int g = ri & 7, rowhalf = ri >> 3;
        int s = q >> 2;
        int reg = ((q >> 1) & 1) * 2 + rowhalf;
        int t = (q & 1) * 2;
        unsigned* base = As + ((mtile * 8 + s) * 32) * 4;
        base[(g * 4 + t) * 4 + reg]     = h2pack(v.x, v.y);
        base[(g * 4 + t + 1) * 4 + reg] = h2pack(v.z, v.w);
    }
    __syncthreads();

#pragma unroll
    for (int s = 0; s < 8; s++) {
        unsigned bh[4][2], bl[4][2];
#pragma unroll
        for (int nf = 0; nf < 4; nf++)
#pragma unroll
            for (int rg = 0; rg < 2; rg++) {
                uint2 b = __ldg(&bimg[((s * 16 + wn * 4 + nf) * 2 + rg) * 32 + lane]);
                bh[nf][rg] = b.x;
                bl[nf][rg] = b.y;
            }
#pragma unroll
        for (int mf = 0; mf < 4; mf++) {
            int mtile = wm * 4 + mf;
            uint4 a = *(const uint4*)&As[(((mtile * 8 + s) * 32) + lane) * 4];
#pragma unroll
            for (int nf = 0; nf < 4; nf++) {
                MMA_F16(c[mf][nf], a.x, a.y, a.z, a.w, bh[nf]);
                MMA_F16(c[mf][nf], a.x, a.y, a.z, a.w, bl[nf]);
            }
        }
    }
}

// ---------------- GEMM: h[M,128] = A[M,128] @ W (fp16 out) ------------------
__global__ __launch_bounds__(256, 2)
void tgemm_kernel(const float* __restrict__ A, int M) {
    extern __shared__ unsigned smu[];
    unsigned* As = smu;        // 32KB

    int tid = threadIdx.x, lane = tid & 31, wid = tid >> 5;
    int wm = wid >> 2, wn = wid & 3;
    long long row0 = (long long)blockIdx.x * 128;

    float c[4][4][4];
#pragma unroll
    for (int a = 0; a < 4; a++)
#pragma unroll
        for (int b = 0; b < 4; b++)
#pragma unroll
            for (int d = 0; d < 4; d++) c[a][b][d] = 0.f;

    mma_mainloop(A, g_bw, As, row0, M, tid, lane, wm, wn, c);

#pragma unroll
    for (int mf = 0; mf < 4; mf++) {
        long long r0 = row0 + wm * 64 + mf * 16 + (lane >> 2);
#pragma unroll
        for (int nf = 0; nf < 4; nf++) {
            int ch = wn * 16 + nf * 4 + (lane & 3);   // half2 column index
            if (r0 < M)
                g_hh[r0 * 64 + ch] = __floats2half2_rn(c[mf][nf][0], c[mf][nf][1]);
            if (r0 + 8 < M)
                g_hh[(r0 + 8) * 64 + ch] = __floats2half2_rn(c[mf][nf][2], c[mf][nf][3]);
        }
    }
}

// ---------------- head GEMM (fp16 mma) + fused finisher ----------------------
__global__ __launch_bounds__(256, 2)
void head_mma_kernel(const float* __restrict__ A, float* __restrict__ out, int M) {
    extern __shared__ unsigned smu[];
    unsigned* As = smu;            // 32KB of the 64KB allocation
    float* Cs = (float*)smu;       // reused after mainloop: 128 x 128 floats
    __shared__ float sbias[128];

    int tid = threadIdx.x, lane = tid & 31, wid = tid >> 5;
    int wm = wid >> 2, wn = wid & 3;
    long long row0 = (long long)blockIdx.x * 128;

    if (tid < 128) sbias[tid] = (tid < HEADP) ? g_hb[tid] : 0.f;

    float c[4][4][4];
#pragma unroll
    for (int a = 0; a < 4; a++)
#pragma unroll
        for (int b = 0; b < 4; b++)
#pragma unroll
            for (int d = 0; d < 4; d++) c[a][b][d] = 0.f;

    mma_mainloop(A, g_bw2, As, row0, M, tid, lane, wm, wn, c);
    __syncthreads();   // all warps done reading As before Cs overwrite

    // stage C into SMEM (stride 128 -> finisher reads are conflict-free)
#pragma unroll
    for (int mf = 0; mf < 4; mf++) {
        int r0 = wm * 64 + mf * 16 + (lane >> 2);
#pragma unroll
        for (int nf = 0; nf < 4; nf++) {
            int col = wn * 32 + nf * 8 + 2 * (lane & 3);
            *(float2*)&Cs[r0 * 128 + col] = make_float2(c[mf][nf][0], c[mf][nf][1]);
            *(float2*)&Cs[(r0 + 8) * 128 + col] = make_float2(c[mf][nf][2], c[mf][nf][3]);
        }
    }
    __syncthreads();

    float* out_main = out;                     // [M,64]
    float* out_sim  = out + (size_t)M * 64;    // [M,40]
    float* out_hom  = out + (size_t)M * 104;   // [M]
    float* out_ent  = out + (size_t)M * 105;   // [M]

    for (int i = 0; i < 16; i++) {
        int row = wid * 16 + i;
        long long gr = row0 + row;
        if (gr >= M) break;
        const float* g = Cs + row * 128;

        // log_softmax over cols [0,64)
        float a = g[lane] + sbias[lane];
        float b = g[32 + lane] + sbias[32 + lane];
        float m1 = fmaxf(a, b);
#pragma unroll
        for (int o = 16; o; o >>= 1)
            m1 = fmaxf(m1, __shfl_xor_sync(0xffffffffu, m1, o));
        float s = expf(a - m1) + expf(b - m1);
#pragma unroll
        for (int o = 16; o; o >>= 1) s += __shfl_xor_sync(0xffffffffu, s, o);
        float ls = m1 + logf(s);
        out_main[gr * 64 + lane]      = a - ls;
        out_main[gr * 64 + 32 + lane] = b - ls;

        // softmax over cols [64,104)
        float u = g[64 + lane] + sbias[64 + lane];
        float v2 = (lane < 8) ? g[96 + lane] + sbias[96 + lane] : -3.0e38f;
        float m2 = fmaxf(u, v2);
#pragma unroll
        for (int o = 16; o; o >>= 1)
            m2 = fmaxf(m2, __shfl_xor_sync(0xffffffffu, m2, o));
        float e1 = expf(u - m2);
        float e2 = (lane < 8) ? expf(v2 - m2) : 0.f;
        float s2 = e1 + e2;
#pragma unroll
        for (int o = 16; o; o >>= 1) s2 += __shfl_xor_sync(0xffffffffu, s2, o);
        float inv = 1.f / s2;
        out_sim[gr * 40 + lane] = e1 * inv;
        if (lane < 8) out_sim[gr * 40 + 32 + lane] = e2 * inv;

        // sigmoids
        if (lane == 0) out_hom[gr] = 1.f / (1.f + expf(-(g[104] + sbias[104])));
        if (lane == 1) out_ent[gr] = 1.f / (1.f + expf(-(g[105] + sbias[105])));
    }
}

// ---------------- CSR gather aggregation (fp16 src, fp32 accum) -------------
// mode 1: +b1, BN(eval), ReLU.   mode 2: +b2.   4-way unrolled gather (MLP=4).
__global__ void agg_kernel(int n, int mode,
                           const float* __restrict__ bias,
                           const float* __restrict__ gamma,
                           const float* __restrict__ beta,
                           const float* __restrict__ mean,
                           const float* __restrict__ var) {
    int node = blockIdx.x * (blockDim.x >> 5) + (threadIdx.x >> 5);
    if (node >= n) return;
    int l = threadIdx.x & 31;

    float d = g_dinv[node];

    float4 a0 = ldh4(g_hh + (size_t)node * 64 + 2 * l);
    float d2 = d * d;
    a0.x *= d2; a0.y *= d2; a0.z *= d2; a0.w *= d2;
    float4 a1 = make_float4(0.f, 0.f, 0.f, 0.f);
    float4 a2 = make_float4(0.f, 0.f, 0.f, 0.f);
    float4 a3 = make_float4(0.f, 0.f, 0.f, 0.f);

    int s = g_rowptr[node], e2 = g_rowptr[node + 1];
    for (int base = s; base < e2; base += 32) {
        int idx = base + l;
        int r = (idx < e2) ? g_src[idx] : 0;
        float dr = (idx < e2) ? g_dinv[r] * d : 0.f;
        int m = e2 - base; if (m > 32) m = 32;
        int j = 0;
        for (; j + 4 <= m; j += 4) {
            int r0 = __shfl_sync(0xffffffffu, r, j);
            int r1 = __shfl_sync(0xffffffffu, r, j + 1);
            int r2 = __shfl_sync(0xffffffffu, r, j + 2);
            int r3 = __shfl_sync(0xffffffffu, r, j + 3);
            float n0 = __shfl_sync(0xffffffffu, dr, j);
            float n1 = __shfl_sync(0xffffffffu, dr, j + 1);
            float n2 = __shfl_sync(0xffffffffu, dr, j + 2);
            float n3 = __shfl_sync(0xffffffffu, dr, j + 3);
            float4 v0 = ldh4(g_hh + (size_t)r0 * 64 + 2 * l);
            float4 v1 = ldh4(g_hh + (size_t)r1 * 64 + 2 * l);
            float4 v2 = ldh4(g_hh + (size_t)r2 * 64 + 2 * l);
            float4 v3 = ldh4(g_hh + (size_t)r3 * 64 + 2 * l);
            a0.x += v0.x * n0; a0.y += v0.y * n0; a0.z += v0.z * n0; a0.w += v0.w * n0;
            a1.x += v1.x * n1; a1.y += v1.y * n1; a1.z += v1.z * n1; a1.w += v1.w * n1;
            a2.x += v2.x * n2; a2.y += v2.y * n2; a2.z += v2.z * n2; a2.w += v2.w * n2;
            a3.x += v3.x * n3; a3.y += v3.y * n3; a3.z += v3.z * n3; a3.w += v3.w * n3;
        }
        for (; j < m; j++) {
            int r0 = __shfl_sync(0xffffffffu, r, j);
            float n0 = __shfl_sync(0xffffffffu, dr, j);
            float4 v0 = ldh4(g_hh + (size_t)r0 * 64 + 2 * l);
            a0.x += v0.x * n0; a0.y += v0.y * n0; a0.z += v0.z * n0; a0.w += v0.w * n0;
        }
    }
    a0.x += a1.x + a2.x + a3.x;
    a0.y += a1.y + a2.y + a3.y;
    a0.z += a1.z + a2.z + a3.z;
    a0.w += a1.w + a2.w + a3.w;

    int c0 = 4 * l;
    float outv[4] = {a0.x, a0.y, a0.z, a0.w};
    if (mode == 1) {
#pragma unroll
        for (int m = 0; m < 4; m++) {
            int c = c0 + m;
            float v = outv[m] + bias[c];
            float sc = gamma[c] * rsqrtf(var[c] + 1e-5f);
            v = (v - mean[c]) * sc + beta[c];
            outv[m] = fmaxf(v, 0.f);
        }
    } else {
#pragma unroll
        for (int m = 0; m < 4; m++) outv[m] += bias[c0 + m];
    }
    *(float4*)(g_agg + (size_t)node * F + c0) =
        make_float4(outv[0], outv[1], outv[2], outv[3]);
}

// ---------------- launch ------------------------------------------------------
extern "C" void kernel_launch(void* const* d_in, const int* in_sizes, int n_in,
                              void* d_out, int out_size) {
    const float* x     = (const float*)d_in[0];
    const void*  eidx  = d_in[1];
    const float* w1    = (const float*)d_in[2];
    const float* b1    = (const float*)d_in[3];
    const float* w2    = (const float*)d_in[4];
    const float* b2    = (const float*)d_in[5];
    const float* gamma = (const float*)d_in[6];
    const float* beta  = (const float*)d_in[7];
    const float* mean  = (const float*)d_in[8];
    const float* var   = (const float*)d_in[9];
    const float* cls_w = (const float*)d_in[10];
    const float* cls_b = (const float*)d_in[11];
    const float* sim_w = (const float*)d_in[12];
    const float* sim_b = (const float*)d_in[13];
    const float* hom_w = (const float*)d_in[14];
    const float* hom_b = (const float*)d_in[15];
    const float* ent_w = (const float*)d_in[16];
    const float* ent_b = (const float*)d_in[17];

    int N = in_sizes[0] / F;
    long long E = (long long)in_sizes[1] / 2;
    float* out = (float*)d_out;

    float* p_agg = nullptr;
    uint2* p_bw = nullptr;
    cudaGetSymbolAddress((void**)&p_agg, g_agg);
    cudaGetSymbolAddress((void**)&p_bw, g_bw);

    size_t smemT = 8192 * sizeof(unsigned);               // 32 KB (fp16 A tile)
    size_t smemH = 128 * 128 * sizeof(float);             // 64 KB (C staging)
    cudaFuncSetAttribute(tgemm_kernel, cudaFuncAttributeMaxDynamicSharedMemorySize,
                         (int)smemT);
    cudaFuncSetAttribute(head_mma_kernel, cudaFuncAttributeMaxDynamicSharedMemorySize,
                         (int)smemH);

    int tb = 256;
    int nscan = (N + SCHUNK - 1) / SCHUNK;
    int tgG = (N + 127) / 128;

    // order chosen so tgemm1 is OUR index 3 == ncu's global launch 5
    prep_w_kernel<<<32, 256>>>(w1, p_bw);                              // 0
    zdetect_kernel<<<(N + tb - 1) / tb, tb>>>((const int*)eidx, N);    // 1
    count_kernel<<<(unsigned)((E + tb - 1) / tb), tb>>>(eidx, E);      // 2
    tgemm_kernel<<<tgG, tb, smemT>>>(x, N);                            // 3 <- ncu
    scan1_kernel<<<nscan, SCHUNK>>>(N);                                // 4
    scan3_kernel<<<nscan, SCHUNK>>>(N, nscan);                         // 5
    fill_kernel<<<(unsigned)((E + tb - 1) / tb), tb>>>(eidx, E);       // 6
    agg_kernel<<<(N + 7) / 8, tb>>>(N, 1, b1, gamma, beta, mean, var); // 7

    // layer 2
    prep_w_kernel<<<32, 256>>>(w2, p_bw);
    tgemm_kernel<<<tgG, tb, smemT>>>(p_agg, N);
    agg_kernel<<<(N + 7) / 8, tb>>>(N, 2, b2, nullptr, nullptr, nullptr, nullptr);

    // heads (mma + fused finisher)
    prep_head_kernel<<<32, 256>>>(cls_w, cls_b, sim_w, sim_b,
                                  hom_w, hom_b, ent_w, ent_b);
    head_mma_kernel<<<tgG, tb, smemH>>>(p_agg, out, N);
}

// round 15
// speedup vs baseline: 1.1900x; 1.0561x over previous
#include <cuda_runtime.h>
#include <cuda_fp16.h>
#include <math.h>
#include <stdint.h>

#define NMAX 100000
#define EMAX 1600000
#define F 128
#define HEADP 108
#define SCHUNK 512

// ---------------- scratch (static device globals; no allocation allowed) ---
__device__ __half2 g_hh[(size_t)NMAX * 64];   // GEMM output (fp16) / gather src
__device__ float g_agg[(size_t)NMAX * F];     // aggregation output (fp32)
__device__ float g_dinv[NMAX];
__device__ int   g_deg[NMAX];
__device__ int   g_rowptr[NMAX + 1];
__device__ int   g_fill[NMAX];
__device__ int   g_src[EMAX];                 // CSR (by destination) source ids
__device__ int   g_bsum[256];
__device__ float g_hb[HEADP];
__device__ int   g_is64;
// W fragment images (plain fp16): [8 k16-steps][16 ntiles][32 lanes][2 regs]
__device__ uint2 g_bw[4096];                  // mainline layer weights (32KB)
__device__ uint2 g_bw2[4096];                 // packed head weights

#define MMA_F16(cc, a0, a1, a2, a3, b0, b1)                                    \
    asm volatile(                                                              \
        "mma.sync.aligned.m16n8k16.row.col.f32.f16.f16.f32 "                   \
        "{%0,%1,%2,%3},{%4,%5,%6,%7},{%8,%9},{%0,%1,%2,%3};"                   \
        : "+f"((cc)[0]), "+f"((cc)[1]), "+f"((cc)[2]), "+f"((cc)[3])           \
        : "r"(a0), "r"(a1), "r"(a2), "r"(a3), "r"(b0), "r"(b1))

// load 4 consecutive h cols (2 half2) and widen to float4
__device__ __forceinline__ float4 ldh4(const __half2* p) {
    uint2 u = __ldg((const uint2*)p);
    __half2 h0 = *(__half2*)&u.x;
    __half2 h1 = *(__half2*)&u.y;
    float2 f0 = __half22float2(h0);
    float2 f1 = __half22float2(h1);
    return make_float4(f0.x, f0.y, f1.x, f1.y);
}

__device__ __forceinline__ unsigned h2pack(float v0, float v1) {
    __half2 h = __floats2half2_rn(v0, v1);
    return *(unsigned*)&h;
}

// ---------------- detect dtype + zero degrees (fused) ----------------------
__global__ void zdetect_kernel(const int* __restrict__ e, int n) {
    int i = blockIdx.x * blockDim.x + threadIdx.x;
    if (i < n) g_deg[i] = 0;
    if (blockIdx.x == 0 && threadIdx.x < 32) {
        int l = threadIdx.x;
        int bad = 0;
        for (int j = l; j < 256; j += 32)
            if (e[2 * j + 1] != 0) bad = 1;
        unsigned b = __ballot_sync(0xffffffffu, bad);
        if (l == 0) g_is64 = (b == 0) ? 1 : 0;
    }
}

__device__ __forceinline__ int ldidx(const void* p, long long i, int is64) {
    return is64 ? (int)((const long long*)p)[i] : ((const int*)p)[i];
}

// ---------------- count degrees (direct edge_index read) --------------------
__global__ void count_kernel(const void* __restrict__ eidx, long long E) {
    long long t = (long long)blockIdx.x * blockDim.x + threadIdx.x;
    if (t >= E) return;
    atomicAdd(&g_deg[ldidx(eidx, E + t, g_is64)], 1);
}

// ---------------- hierarchical scan (2 stages) ------------------------------
__global__ void scan1_kernel(int n) {
    __shared__ int sh[SCHUNK];
    int t = threadIdx.x;
    int i = blockIdx.x * SCHUNK + t;
    sh[t] = (i < n) ? g_deg[i] : 0;
    __syncthreads();
#pragma unroll
    for (int off = SCHUNK / 2; off; off >>= 1) {
        if (t < off) sh[t] += sh[t + off];
        __syncthreads();
    }
    if (t == 0) g_bsum[blockIdx.x] = sh[0];
}

__global__ void scan3_kernel(int n, int nb) {
    __shared__ int bs[256];
    __shared__ int sh[SCHUNK];
    int t = threadIdx.x;
    if (t < 256) bs[t] = (t < nb) ? g_bsum[t] : 0;
    __syncthreads();
#pragma unroll
    for (int off = 1; off < 256; off <<= 1) {
        int u = (t < 256 && t >= off) ? bs[t - off] : 0;
        __syncthreads();
        if (t < 256) bs[t] += u;
        __syncthreads();
    }
    int boff = (blockIdx.x == 0) ? 0 : bs[blockIdx.x - 1];
    if (blockIdx.x == 0 && t == 0) g_rowptr[n] = bs[nb - 1];

    int i = blockIdx.x * SCHUNK + t;
    int d = (i < n) ? g_deg[i] : 0;
    sh[t] = d;
    __syncthreads();
#pragma unroll
    for (int off = 1; off < SCHUNK; off <<= 1) {
        int u = (t >= off) ? sh[t - off] : 0;
        __syncthreads();
        sh[t] += u;
        __syncthreads();
    }
    if (i < n) {
        int pre = boff + sh[t] - d;
        g_rowptr[i] = pre;
        g_fill[i]   = pre;
        g_dinv[i]   = rsqrtf((float)(d + 1));  // +1 self-loop
    }
}

__global__ void fill_kernel(const void* __restrict__ eidx, long long E) {
    long long e = (long long)blockIdx.x * blockDim.x + threadIdx.x;
    if (e >= E) return;
    int is64 = g_is64;
    int r = ldidx(eidx, e, is64);
    int c = ldidx(eidx, E + e, is64);
    int pos = atomicAdd(&g_fill[c], 1);
    g_src[pos] = r;
}

// ---------------- W prep: plain fp16 m16n8k16 B-fragment image --------------
// For k-pair (k=2kp,2kp+1) x col n of W[128][128]:
//   s = k>>4, kw = k&15, reg = kw>>3, t = (kw&7)>>1, lane = (n&7)*4+t
//   tile = s*16 + n/8; u32 image idx = (tile*32 + lane)*2 + reg
__global__ void prep_w_kernel(const float* __restrict__ W, uint2* __restrict__ img) {
    int p = blockIdx.x * blockDim.x + threadIdx.x;
    if (p >= 8192) return;
    int kp = p >> 7, n = p & 127;
    int k = 2 * kp;
    float v0 = W[k * 128 + n];
    float v1 = W[(k + 1) * 128 + n];
    int s = k >> 4, kw = k & 15;
    int reg = kw >> 3, t = (kw & 7) >> 1;
    int tile = s * 16 + (n >> 3);
    ((unsigned*)img)[(tile * 32 + (n & 7) * 4 + t) * 2 + reg] = h2pack(v0, v1);
}

// same, gathering packed head weights (cls|sim|hom|ent, zero-padded to 128)
__global__ void prep_head_kernel(const float* __restrict__ cls_w,
                                 const float* __restrict__ cls_b,
                                 const float* __restrict__ sim_w,
                                 const float* __restrict__ sim_b,
                                 const float* __restrict__ hom_w,
                                 const float* __restrict__ hom_b,
                                 const float* __restrict__ ent_w,
                                 const float* __restrict__ ent_b) {
    int p = blockIdx.x * blockDim.x + threadIdx.x;
    if (p < HEADP) {
        float v = 0.f;
        if (p < 64)        v = cls_b[p];
        else if (p < 104)  v = sim_b[p - 64];
        else if (p == 104) v = hom_b[0];
        else if (p == 105) v = ent_b[0];
        g_hb[p] = v;
    }
    if (p >= 8192) return;
    int kp = p >> 7, n = p & 127;
    int k = 2 * kp;
    float v0 = 0.f, v1 = 0.f;
    if (n < 64)        { v0 = cls_w[k * 64 + n];        v1 = cls_w[(k + 1) * 64 + n]; }
    else if (n < 104)  { v0 = sim_w[k * 40 + n - 64];   v1 = sim_w[(k + 1) * 40 + n - 64]; }
    else if (n == 104) { v0 = hom_w[k];                 v1 = hom_w[k + 1]; }
    else if (n == 105) { v0 = ent_w[k];                 v1 = ent_w[k + 1]; }
    int s = k >> 4, kw = k & 15;
    int reg = kw >> 3, t = (kw & 7) >> 1;
    int tile = s * 16 + (n >> 3);
    ((unsigned*)g_bw2)[(tile * 32 + (n & 7) * 4 + t) * 2 + reg] = h2pack(v0, v1);
}

// ---------------- fully-fp16 mma mainloop ------------------------------------
// Block: 128x128, 8 warps (2M x 4N), warp tile 64x32, 8 k16-steps.
// A staged as plain fp16 in SMEM: [mtile(8)][s(8)][lane(32)][reg(4)] unsigned
// (32KB) -> one conflict-free LDS.128 per A fragment. B fragments: one LDG.64
// per (s,nf) from the 32KB L1-resident image. 1 MMA per (mf,nf,s).
__device__ __forceinline__ void mma_mainloop(const float* __restrict__ A,
                                             const uint2* __restrict__ bimg,
                                             unsigned* As,
                                             long long row0, int M,
                                             int tid, int lane, int wm, int wn,
                                             float c[4][4][4]) {
    // stage ALL of A as plain fp16: 4096 float4 loads block-wide
    for (int idx = tid; idx < 4096; idx += 256) {
        int r = idx >> 5, q = idx & 31;           // row, float4-col
        long long gr = row0 + r;
        float4 v = make_float4(0.f, 0.f, 0.f, 0.f);
        if (gr < M) v = __ldg((const float4*)(A + gr * F) + q);
        int mtile = r >> 4, ri = r & 15;
        int g = ri & 7, rowhalf = ri >> 3;
        int s = q >> 2;
        int reg = ((q >> 1) & 1) * 2 + rowhalf;
        int t = (q & 1) * 2;
        unsigned* base = As + ((mtile * 8 + s) * 32) * 4;
        base[(g * 4 + t) * 4 + reg]     = h2pack(v.x, v.y);
        base[(g * 4 + t + 1) * 4 + reg] = h2pack(v.z, v.w);
    }
    __syncthreads();

#pragma unroll
    for (int s = 0; s < 8; s++) {
        uint2 b[4];
#pragma unroll
        for (int nf = 0; nf < 4; nf++)
            b[nf] = __ldg(&bimg[(s * 16 + wn * 4 + nf) * 32 + lane]);
#pragma unroll
        for (int mf = 0; mf < 4; mf++) {
            int mtile = wm * 4 + mf;
            uint4 a = *(const uint4*)&As[(((mtile * 8 + s) * 32) + lane) * 4];
#pragma unroll
            for (int nf = 0; nf < 4; nf++)
                MMA_F16(c[mf][nf], a.x, a.y, a.z, a.w, b[nf].x, b[nf].y);
        }
    }
}

// ---------------- GEMM: h[M,128] = A[M,128] @ W (fp16 out) ------------------
__global__ __launch_bounds__(256, 2)
void tgemm_kernel(const float* __restrict__ A, int M) {
    extern __shared__ unsigned smu[];
    unsigned* As = smu;        // 32KB

    int tid = threadIdx.x, lane = tid & 31, wid = tid >> 5;
    int wm = wid >> 2, wn = wid & 3;
    long long row0 = (long long)blockIdx.x * 128;

    float c[4][4][4];
#pragma unroll
    for (int a = 0; a < 4; a++)
#pragma unroll
        for (int b = 0; b < 4; b++)
#pragma unroll
            for (int d = 0; d < 4; d++) c[a][b][d] = 0.f;

    mma_mainloop(A, g_bw, As, row0, M, tid, lane, wm, wn, c);

#pragma unroll
    for (int mf = 0; mf < 4; mf++) {
        long long r0 = row0 + wm * 64 + mf * 16 + (lane >> 2);
#pragma unroll
        for (int nf = 0; nf < 4; nf++) {
            int ch = wn * 16 + nf * 4 + (lane & 3);   // half2 column index
            if (r0 < M)
                g_hh[r0 * 64 + ch] = __floats2half2_rn(c[mf][nf][0], c[mf][nf][1]);
            if (r0 + 8 < M)
                g_hh[(r0 + 8) * 64 + ch] = __floats2half2_rn(c[mf][nf][2], c[mf][nf][3]);
        }
    }
}

// ---------------- head GEMM (fp16 mma) + fused finisher ----------------------
__global__ __launch_bounds__(256, 2)
void head_mma_kernel(const float* __restrict__ A, float* __restrict__ out, int M) {
    extern __shared__ unsigned smu[];
    unsigned* As = smu;            // 32KB of the 64KB allocation
    float* Cs = (float*)smu;       // reused after mainloop: 128 x 128 floats
    __shared__ float sbias[128];

    int tid = threadIdx.x, lane = tid & 31, wid = tid >> 5;
    int wm = wid >> 2, wn = wid & 3;
    long long row0 = (long long)blockIdx.x * 128;

    if (tid < 128) sbias[tid] = (tid < HEADP) ? g_hb[tid] : 0.f;

    float c[4][4][4];
#pragma unroll
    for (int a = 0; a < 4; a++)
#pragma unroll
        for (int b = 0; b < 4; b++)
#pragma unroll
            for (int d = 0; d < 4; d++) c[a][b][d] = 0.f;

    mma_mainloop(A, g_bw2, As, row0, M, tid, lane, wm, wn, c);
    __syncthreads();   // all warps done reading As before Cs overwrite

    // stage C into SMEM (stride 128 -> finisher reads are conflict-free)
#pragma unroll
    for (int mf = 0; mf < 4; mf++) {
        int r0 = wm * 64 + mf * 16 + (lane >> 2);
#pragma unroll
        for (int nf = 0; nf < 4; nf++) {
            int col = wn * 32 + nf * 8 + 2 * (lane & 3);
            *(float2*)&Cs[r0 * 128 + col] = make_float2(c[mf][nf][0], c[mf][nf][1]);
            *(float2*)&Cs[(r0 + 8) * 128 + col] = make_float2(c[mf][nf][2], c[mf][nf][3]);
        }
    }
    __syncthreads();

    float* out_main = out;                     // [M,64]
    float* out_sim  = out + (size_t)M * 64;    // [M,40]
    float* out_hom  = out + (size_t)M * 104;   // [M]
    float* out_ent  = out + (size_t)M * 105;   // [M]

    for (int i = 0; i < 16; i++) {
        int row = wid * 16 + i;
        long long gr = row0 + row;
        if (gr >= M) break;
        const float* g = Cs + row * 128;

        // log_softmax over cols [0,64)
        float a = g[lane] + sbias[lane];
        float b = g[32 + lane] + sbias[32 + lane];
        float m1 = fmaxf(a, b);
#pragma unroll
        for (int o = 16; o; o >>= 1)
            m1 = fmaxf(m1, __shfl_xor_sync(0xffffffffu, m1, o));
        float s = expf(a - m1) + expf(b - m1);
#pragma unroll
        for (int o = 16; o; o >>= 1) s += __shfl_xor_sync(0xffffffffu, s, o);
        float ls = m1 + logf(s);
        out_main[gr * 64 + lane]      = a - ls;
        out_main[gr * 64 + 32 + lane] = b - ls;

        // softmax over cols [64,104)
        float u = g[64 + lane] + sbias[64 + lane];
        float v2 = (lane < 8) ? g[96 + lane] + sbias[96 + lane] : -3.0e38f;
        float m2 = fmaxf(u, v2);
#pragma unroll
        for (int o = 16; o; o >>= 1)
            m2 = fmaxf(m2, __shfl_xor_sync(0xffffffffu, m2, o));
        float e1 = expf(u - m2);
        float e2 = (lane < 8) ? expf(v2 - m2) : 0.f;
        float s2 = e1 + e2;
#pragma unroll
        for (int o = 16; o; o >>= 1) s2 += __shfl_xor_sync(0xffffffffu, s2, o);
        float inv = 1.f / s2;
        out_sim[gr * 40 + lane] = e1 * inv;
        if (lane < 8) out_sim[gr * 40 + 32 + lane] = e2 * inv;

        // sigmoids
        if (lane == 0) out_hom[gr] = 1.f / (1.f + expf(-(g[104] + sbias[104])));
        if (lane == 1) out_ent[gr] = 1.f / (1.f + expf(-(g[105] + sbias[105])));
    }
}

// ---------------- CSR gather aggregation (fp16 src, fp32 accum) -------------
// mode 1: +b1, BN(eval), ReLU.   mode 2: +b2.   4-way unrolled gather (MLP=4).
__global__ void agg_kernel(int n, int mode,
                           const float* __restrict__ bias,
                           const float* __restrict__ gamma,
                           const float* __restrict__ beta,
                           const float* __restrict__ mean,
                           const float* __restrict__ var) {
    int node = blockIdx.x * (blockDim.x >> 5) + (threadIdx.x >> 5);
    if (node >= n) return;
    int l = threadIdx.x & 31;

    float d = g_dinv[node];

    float4 a0 = ldh4(g_hh + (size_t)node * 64 + 2 * l);
    float d2 = d * d;
    a0.x *= d2; a0.y *= d2; a0.z *= d2; a0.w *= d2;
    float4 a1 = make_float4(0.f, 0.f, 0.f, 0.f);
    float4 a2 = make_float4(0.f, 0.f, 0.f, 0.f);
    float4 a3 = make_float4(0.f, 0.f, 0.f, 0.f);

    int s = g_rowptr[node], e2 = g_rowptr[node + 1];
    for (int base = s; base < e2; base += 32) {
        int idx = base + l;
        int r = (idx < e2) ? g_src[idx] : 0;
        float dr = (idx < e2) ? g_dinv[r] * d : 0.f;
        int m = e2 - base; if (m > 32) m = 32;
        int j = 0;
        for (; j + 4 <= m; j += 4) {
            int r0 = __shfl_sync(0xffffffffu, r, j);
            int r1 = __shfl_sync(0xffffffffu, r, j + 1);
            int r2 = __shfl_sync(0xffffffffu, r, j + 2);
            int r3 = __shfl_sync(0xffffffffu, r, j + 3);
            float n0 = __shfl_sync(0xffffffffu, dr, j);
            float n1 = __shfl_sync(0xffffffffu, dr, j + 1);
            float n2 = __shfl_sync(0xffffffffu, dr, j + 2);
            float n3 = __shfl_sync(0xffffffffu, dr, j + 3);
            float4 v0 = ldh4(g_hh + (size_t)r0 * 64 + 2 * l);
            float4 v1 = ldh4(g_hh + (size_t)r1 * 64 + 2 * l);
            float4 v2 = ldh4(g_hh + (size_t)r2 * 64 + 2 * l);
            float4 v3 = ldh4(g_hh + (size_t)r3 * 64 + 2 * l);
            a0.x += v0.x * n0; a0.y += v0.y * n0; a0.z += v0.z * n0; a0.w += v0.w * n0;
            a1.x += v1.x * n1; a1.y += v1.y * n1; a1.z += v1.z * n1; a1.w += v1.w * n1;
            a2.x += v2.x * n2; a2.y += v2.y * n2; a2.z += v2.z * n2; a2.w += v2.w * n2;
            a3.x += v3.x * n3; a3.y += v3.y * n3; a3.z += v3.z * n3; a3.w += v3.w * n3;
        }
        for (; j < m; j++) {
            int r0 = __shfl_sync(0xffffffffu, r, j);
            float n0 = __shfl_sync(0xffffffffu, dr, j);
            float4 v0 = ldh4(g_hh + (size_t)r0 * 64 + 2 * l);
            a0.x += v0.x * n0; a0.y += v0.y * n0; a0.z += v0.z * n0; a0.w += v0.w * n0;
        }
    }
    a0.x += a1.x + a2.x + a3.x;
    a0.y += a1.y + a2.y + a3.y;
    a0.z += a1.z + a2.z + a3.z;
    a0.w += a1.w + a2.w + a3.w;

    int c0 = 4 * l;
    float outv[4] = {a0.x, a0.y, a0.z, a0.w};
    if (mode == 1) {
#pragma unroll
        for (int m = 0; m < 4; m++) {
            int c = c0 + m;
            float v = outv[m] + bias[c];
            float sc = gamma[c] * rsqrtf(var[c] + 1e-5f);
            v = (v - mean[c]) * sc + beta[c];
            outv[m] = fmaxf(v, 0.f);
        }
    } else {
#pragma unroll
        for (int m = 0; m < 4; m++) outv[m] += bias[c0 + m];
    }
    *(float4*)(g_agg + (size_t)node * F + c0) =
        make_float4(outv[0], outv[1], outv[2], outv[3]);
}

// ---------------- launch ------------------------------------------------------
extern "C" void kernel_launch(void* const* d_in, const int* in_sizes, int n_in,
                              void* d_out, int out_size) {
    const float* x     = (const float*)d_in[0];
    const void*  eidx  = d_in[1];
    const float* w1    = (const float*)d_in[2];
    const float* b1    = (const float*)d_in[3];
    const float* w2    = (const float*)d_in[4];
    const float* b2    = (const float*)d_in[5];
    const float* gamma = (const float*)d_in[6];
    const float* beta  = (const float*)d_in[7];
    const float* mean  = (const float*)d_in[8];
    const float* var   = (const float*)d_in[9];
    const float* cls_w = (const float*)d_in[10];
    const float* cls_b = (const float*)d_in[11];
    const float* sim_w = (const float*)d_in[12];
    const float* sim_b = (const float*)d_in[13];
    const float* hom_w = (const float*)d_in[14];
    const float* hom_b = (const float*)d_in[15];
    const float* ent_w = (const float*)d_in[16];
    const float* ent_b = (const float*)d_in[17];

    int N = in_sizes[0] / F;
    long long E = (long long)in_sizes[1] / 2;
    float* out = (float*)d_out;

    float* p_agg = nullptr;
    uint2* p_bw = nullptr;
    cudaGetSymbolAddress((void**)&p_agg, g_agg);
    cudaGetSymbolAddress((void**)&p_bw, g_bw);

    size_t smemT = 8192 * sizeof(unsigned);               // 32 KB (fp16 A tile)
    size_t smemH = 128 * 128 * sizeof(float);             // 64 KB (C staging)
    cudaFuncSetAttribute(tgemm_kernel, cudaFuncAttributeMaxDynamicSharedMemorySize,
                         (int)smemT);
    cudaFuncSetAttribute(head_mma_kernel, cudaFuncAttributeMaxDynamicSharedMemorySize,
                         (int)smemH);

    int tb = 256;
    int nscan = (N + SCHUNK - 1) / SCHUNK;
    int tgG = (N + 127) / 128;

    // order chosen so tgemm1 is OUR index 3 == ncu's global launch 5
    prep_w_kernel<<<32, 256>>>(w1, p_bw);                              // 0
    zdetect_kernel<<<(N + tb - 1) / tb, tb>>>((const int*)eidx, N);    // 1
    count_kernel<<<(unsigned)((E + tb - 1) / tb), tb>>>(eidx, E);      // 2
    tgemm_kernel<<<tgG, tb, smemT>>>(x, N);                            // 3 <- ncu
    scan1_kernel<<<nscan, SCHUNK>>>(N);                                // 4
    scan3_kernel<<<nscan, SCHUNK>>>(N, nscan);                         // 5
    fill_kernel<<<(unsigned)((E + tb - 1) / tb), tb>>>(eidx, E);       // 6
    agg_kernel<<<(N + 7) / 8, tb>>>(N, 1, b1, gamma, beta, mean, var); // 7

    // layer 2
    prep_w_kernel<<<32, 256>>>(w2, p_bw);
    tgemm_kernel<<<tgG, tb, smemT>>>(p_agg, N);
    agg_kernel<<<(N + 7) / 8, tb>>>(N, 2, b2, nullptr, nullptr, nullptr, nullptr);

    // heads (mma + fused finisher)
    prep_head_kernel<<<32, 256>>>(cls_w, cls_b, sim_w, sim_b,
                                  hom_w, hom_b, ent_w, ent_b);
    head_mma_kernel<<<tgG, tb, smemH>>>(p_agg, out, N);
}

// round 16
// speedup vs baseline: 1.3163x; 1.1061x over previous
#include <cuda_runtime.h>
#include <cuda_fp16.h>
#include <math.h>
#include <stdint.h>

#define NMAX 100000
#define EMAX 1600000
#define F 128
#define HEADP 108
#define SCHUNK 512

// ---------------- scratch (static device globals; no allocation allowed) ---
__device__ __half2 g_hh[(size_t)NMAX * 64];   // GEMM output (fp16) / gather src
__device__ float g_agg[(size_t)NMAX * F];     // aggregation output (fp32)
__device__ float g_dinv[NMAX];
__device__ int   g_deg[NMAX];
__device__ int   g_rowptr[NMAX + 1];
__device__ int   g_fill[NMAX];
__device__ int   g_src[EMAX];                 // CSR (by destination) source ids
__device__ int   g_bsum[256];
__device__ float g_hb[HEADP];
__device__ int   g_is64;
// W fragment images (plain fp16): [8 k16-steps][16 ntiles][32 lanes][2 regs]
__device__ uint2 g_bw[4096];                  // mainline layer weights (32KB)
__device__ uint2 g_bw2[4096];                 // packed head weights

#define MMA_F16(cc, a0, a1, a2, a3, b0, b1)                                    \
    asm volatile(                                                              \
        "mma.sync.aligned.m16n8k16.row.col.f32.f16.f16.f32 "                   \
        "{%0,%1,%2,%3},{%4,%5,%6,%7},{%8,%9},{%0,%1,%2,%3};"                   \
        : "+f"((cc)[0]), "+f"((cc)[1]), "+f"((cc)[2]), "+f"((cc)[3])           \
        : "r"(a0), "r"(a1), "r"(a2), "r"(a3), "r"(b0), "r"(b1))

// load 4 consecutive h cols (2 half2) and widen to float4
__device__ __forceinline__ float4 ldh4(const __half2* p) {
    uint2 u = __ldg((const uint2*)p);
    __half2 h0 = *(__half2*)&u.x;
    __half2 h1 = *(__half2*)&u.y;
    float2 f0 = __half22float2(h0);
    float2 f1 = __half22float2(h1);
    return make_float4(f0.x, f0.y, f1.x, f1.y);
}

__device__ __forceinline__ unsigned h2pack(float v0, float v1) {
    __half2 h = __floats2half2_rn(v0, v1);
    return *(unsigned*)&h;
}

// ---------------- detect dtype + zero degrees (fused) ----------------------
__global__ void zdetect_kernel(const int* __restrict__ e, int n) {
    int i = blockIdx.x * blockDim.x + threadIdx.x;
    if (i < n) g_deg[i] = 0;
    if (blockIdx.x == 0 && threadIdx.x < 32) {
        int l = threadIdx.x;
        int bad = 0;
        for (int j = l; j < 256; j += 32)
            if (e[2 * j + 1] != 0) bad = 1;
        unsigned b = __ballot_sync(0xffffffffu, bad);
        if (l == 0) g_is64 = (b == 0) ? 1 : 0;
    }
}

__device__ __forceinline__ int ldidx(const void* p, long long i, int is64) {
    return is64 ? (int)((const long long*)p)[i] : ((const int*)p)[i];
}

// ---------------- count degrees (direct edge_index read) --------------------
__global__ void count_kernel(const void* __restrict__ eidx, long long E) {
    long long t = (long long)blockIdx.x * blockDim.x + threadIdx.x;
    if (t >= E) return;
    atomicAdd(&g_deg[ldidx(eidx, E + t, g_is64)], 1);
}

// ---------------- hierarchical scan (2 stages) ------------------------------
__global__ void scan1_kernel(int n) {
    __shared__ int sh[SCHUNK];
    int t = threadIdx.x;
    int i = blockIdx.x * SCHUNK + t;
    sh[t] = (i < n) ? g_deg[i] : 0;
    __syncthreads();
#pragma unroll
    for (int off = SCHUNK / 2; off; off >>= 1) {
        if (t < off) sh[t] += sh[t + off];
        __syncthreads();
    }
    if (t == 0) g_bsum[blockIdx.x] = sh[0];
}

__global__ void scan3_kernel(int n, int nb) {
    __shared__ int bs[256];
    __shared__ int sh[SCHUNK];
    int t = threadIdx.x;
    if (t < 256) bs[t] = (t < nb) ? g_bsum[t] : 0;
    __syncthreads();
#pragma unroll
    for (int off = 1; off < 256; off <<= 1) {
        int u = (t < 256 && t >= off) ? bs[t - off] : 0;
        __syncthreads();
        if (t < 256) bs[t] += u;
        __syncthreads();
    }
    int boff = (blockIdx.x == 0) ? 0 : bs[blockIdx.x - 1];
    if (blockIdx.x == 0 && t == 0) g_rowptr[n] = bs[nb - 1];

    int i = blockIdx.x * SCHUNK + t;
    int d = (i < n) ? g_deg[i] : 0;
    sh[t] = d;
    __syncthreads();
#pragma unroll
    for (int off = 1; off < SCHUNK; off <<= 1) {
        int u = (t >= off) ? sh[t - off] : 0;
        __syncthreads();
        sh[t] += u;
        __syncthreads();
    }
    if (i < n) {
        int pre = boff + sh[t] - d;
        g_rowptr[i] = pre;
        g_fill[i]   = pre;
        g_dinv[i]   = rsqrtf((float)(d + 1));  // +1 self-loop
    }
}

__global__ void fill_kernel(const void* __restrict__ eidx, long long E) {
    long long e = (long long)blockIdx.x * blockDim.x + threadIdx.x;
    if (e >= E) return;
    int is64 = g_is64;
    int r = ldidx(eidx, e, is64);
    int c = ldidx(eidx, E + e, is64);
    int pos = atomicAdd(&g_fill[c], 1);
    g_src[pos] = r;
}

// ---------------- W prep: plain fp16 m16n8k16 B-fragment image --------------
__global__ void prep_w_kernel(const float* __restrict__ W, uint2* __restrict__ img) {
    int p = blockIdx.x * blockDim.x + threadIdx.x;
    if (p >= 8192) return;
    int kp = p >> 7, n = p & 127;
    int k = 2 * kp;
    float v0 = W[k * 128 + n];
    float v1 = W[(k + 1) * 128 + n];
    int s = k >> 4, kw = k & 15;
    int reg = kw >> 3, t = (kw & 7) >> 1;
    int tile = s * 16 + (n >> 3);
    ((unsigned*)img)[(tile * 32 + (n & 7) * 4 + t) * 2 + reg] = h2pack(v0, v1);
}

// same, gathering packed head weights (cls|sim|hom|ent, zero-padded to 128)
__global__ void prep_head_kernel(const float* __restrict__ cls_w,
                                 const float* __restrict__ cls_b,
                                 const float* __restrict__ sim_w,
                                 const float* __restrict__ sim_b,
                                 const float* __restrict__ hom_w,
                                 const float* __restrict__ hom_b,
                                 const float* __restrict__ ent_w,
                                 const float* __restrict__ ent_b) {
    int p = blockIdx.x * blockDim.x + threadIdx.x;
    if (p < HEADP) {
        float v = 0.f;
        if (p < 64)        v = cls_b[p];
        else if (p < 104)  v = sim_b[p - 64];
        else if (p == 104) v = hom_b[0];
        else if (p == 105) v = ent_b[0];
        g_hb[p] = v;
    }
    if (p >= 8192) return;
    int kp = p >> 7, n = p & 127;
    int k = 2 * kp;
    float v0 = 0.f, v1 = 0.f;
    if (n < 64)        { v0 = cls_w[k * 64 + n];        v1 = cls_w[(k + 1) * 64 + n]; }
    else if (n < 104)  { v0 = sim_w[k * 40 + n - 64];   v1 = sim_w[(k + 1) * 40 + n - 64]; }
    else if (n == 104) { v0 = hom_w[k];                 v1 = hom_w[k + 1]; }
    else if (n == 105) { v0 = ent_w[k];                 v1 = ent_w[k + 1]; }
    int s = k >> 4, kw = k & 15;
    int reg = kw >> 3, t = (kw & 7) >> 1;
    int tile = s * 16 + (n >> 3);
    ((unsigned*)g_bw2)[(tile * 32 + (n & 7) * 4 + t) * 2 + reg] = h2pack(v0, v1);
}

// ---------------- fully-fp16 mma mainloop (512 threads) ----------------------
// Block: 128x128, 16 warps (4M x 4N), warp tile 32x32, 8 k16-steps.
// A staged as plain fp16 in SMEM: [mtile(8)][s(8)][lane(32)][reg(4)] unsigned
// (32KB). Per warp per s: 2 A-LDS.128 + 4 B-LDG.64 + 8 MMAs.
__device__ __forceinline__ void mma_mainloop(const float* __restrict__ A,
                                             const uint2* __restrict__ bimg,
                                             unsigned* As,
                                             long long row0, int M,
                                             int tid, int lane, int wm, int wn,
                                             float c[2][4][4]) {
    // stage ALL of A as plain fp16: 4096 float4 loads block-wide (8/thread)
    for (int idx = tid; idx < 4096; idx += 512) {
        int r = idx >> 5, q = idx & 31;           // row, float4-col
        long long gr = row0 + r;
        float4 v = make_float4(0.f, 0.f, 0.f, 0.f);
        if (gr < M) v = __ldg((const float4*)(A + gr * F) + q);
        int mtile = r >> 4, ri = r & 15;
        int g = ri & 7, rowhalf = ri >> 3;
        int s = q >> 2;
        int reg = ((q >> 1) & 1) * 2 + rowhalf;
        int t = (q & 1) * 2;
        unsigned* base = As + ((mtile * 8 + s) * 32) * 4;
        base[(g * 4 + t) * 4 + reg]     = h2pack(v.x, v.y);
        base[(g * 4 + t + 1) * 4 + reg] = h2pack(v.z, v.w);
    }
    __syncthreads();

#pragma unroll
    for (int s = 0; s < 8; s++) {
        uint2 b[4];
#pragma unroll
        for (int nf = 0; nf < 4; nf++)
            b[nf] = __ldg(&bimg[(s * 16 + wn * 4 + nf) * 32 + lane]);
#pragma unroll
        for (int mf = 0; mf < 2; mf++) {
            int mtile = wm * 2 + mf;
            uint4 a = *(const uint4*)&As[(((mtile * 8 + s) * 32) + lane) * 4];
#pragma unroll
            for (int nf = 0; nf < 4; nf++)
                MMA_F16(c[mf][nf], a.x, a.y, a.z, a.w, b[nf].x, b[nf].y);
        }
    }
}

// ---------------- GEMM: h[M,128] = A[M,128] @ W (fp16 out) ------------------
__global__ __launch_bounds__(512, 2)
void tgemm_kernel(const float* __restrict__ A, int M) {
    extern __shared__ unsigned smu[];
    unsigned* As = smu;        // 32KB

    int tid = threadIdx.x, lane = tid & 31, wid = tid >> 5;
    int wm = wid >> 2, wn = wid & 3;
    long long row0 = (long long)blockIdx.x * 128;

    float c[2][4][4];
#pragma unroll
    for (int a = 0; a < 2; a++)
#pragma unroll
        for (int b = 0; b < 4; b++)
#pragma unroll
            for (int d = 0; d < 4; d++) c[a][b][d] = 0.f;

    mma_mainloop(A, g_bw, As, row0, M, tid, lane, wm, wn, c);

#pragma unroll
    for (int mf = 0; mf < 2; mf++) {
        long long r0 = row0 + wm * 32 + mf * 16 + (lane >> 2);
#pragma unroll
        for (int nf = 0; nf < 4; nf++) {
            int ch = wn * 16 + nf * 4 + (lane & 3);   // half2 column index
            if (r0 < M)
                g_hh[r0 * 64 + ch] = __floats2half2_rn(c[mf][nf][0], c[mf][nf][1]);
            if (r0 + 8 < M)
                g_hh[(r0 + 8) * 64 + ch] = __floats2half2_rn(c[mf][nf][2], c[mf][nf][3]);
        }
    }
}

// ---------------- head GEMM (fp16 mma) + fused finisher ----------------------
__global__ __launch_bounds__(512, 2)
void head_mma_kernel(const float* __restrict__ A, float* __restrict__ out, int M) {
    extern __shared__ unsigned smu[];
    unsigned* As = smu;            // 32KB of the 64KB allocation
    float* Cs = (float*)smu;       // reused after mainloop: 128 x 128 floats
    __shared__ float sbias[128];

    int tid = threadIdx.x, lane = tid & 31, wid = tid >> 5;
    int wm = wid >> 2, wn = wid & 3;
    long long row0 = (long long)blockIdx.x * 128;

    if (tid < 128) sbias[tid] = (tid < HEADP) ? g_hb[tid] : 0.f;

    float c[2][4][4];
#pragma unroll
    for (int a = 0; a < 2; a++)
#pragma unroll
        for (int b = 0; b < 4; b++)
#pragma unroll
            for (int d = 0; d < 4; d++) c[a][b][d] = 0.f;

    mma_mainloop(A, g_bw2, As, row0, M, tid, lane, wm, wn, c);
    __syncthreads();   // all warps done reading As before Cs overwrite

    // stage C into SMEM (stride 128 -> finisher reads are conflict-free)
#pragma unroll
    for (int mf = 0; mf < 2; mf++) {
        int r0 = wm * 32 + mf * 16 + (lane >> 2);
#pragma unroll
        for (int nf = 0; nf < 4; nf++) {
            int col = wn * 32 + nf * 8 + 2 * (lane & 3);
            *(float2*)&Cs[r0 * 128 + col] = make_float2(c[mf][nf][0], c[mf][nf][1]);
            *(float2*)&Cs[(r0 + 8) * 128 + col] = make_float2(c[mf][nf][2], c[mf][nf][3]);
        }
    }
    __syncthreads();

    float* out_main = out;                     // [M,64]
    float* out_sim  = out + (size_t)M * 64;    // [M,40]
    float* out_hom  = out + (size_t)M * 104;   // [M]
    float* out_ent  = out + (size_t)M * 105;   // [M]

    for (int i = 0; i < 8; i++) {
        int row = wid * 8 + i;
        long long gr = row0 + row;
        if (gr >= M) break;
        const float* g = Cs + row * 128;

        // log_softmax over cols [0,64)
        float a = g[lane] + sbias[lane];
        float b = g[32 + lane] + sbias[32 + lane];
        float m1 = fmaxf(a, b);
#pragma unroll
        for (int o = 16; o; o >>= 1)
            m1 = fmaxf(m1, __shfl_xor_sync(0xffffffffu, m1, o));
        float s = expf(a - m1) + expf(b - m1);
#pragma unroll
        for (int o = 16; o; o >>= 1) s += __shfl_xor_sync(0xffffffffu, s, o);
        float ls = m1 + logf(s);
        out_main[gr * 64 + lane]      = a - ls;
        out_main[gr * 64 + 32 + lane] = b - ls;

        // softmax over cols [64,104)
        float u = g[64 + lane] + sbias[64 + lane];
        float v2 = (lane < 8) ? g[96 + lane] + sbias[96 + lane] : -3.0e38f;
        float m2 = fmaxf(u, v2);
#pragma unroll
        for (int o = 16; o; o >>= 1)
            m2 = fmaxf(m2, __shfl_xor_sync(0xffffffffu, m2, o));
        float e1 = expf(u - m2);
        float e2 = (lane < 8) ? expf(v2 - m2) : 0.f;
        float s2 = e1 + e2;
#pragma unroll
        for (int o = 16; o; o >>= 1) s2 += __shfl_xor_sync(0xffffffffu, s2, o);
        float inv = 1.f / s2;
        out_sim[gr * 40 + lane] = e1 * inv;
        if (lane < 8) out_sim[gr * 40 + 32 + lane] = e2 * inv;

        // sigmoids
        if (lane == 0) out_hom[gr] = 1.f / (1.f + expf(-(g[104] + sbias[104])));
        if (lane == 1) out_ent[gr] = 1.f / (1.f + expf(-(g[105] + sbias[105])));
    }
}

// ---------------- CSR gather aggregation (fp16 src, fp32 accum) -------------
// mode 1: +b1, BN(eval), ReLU.   mode 2: +b2.   4-way unrolled gather (MLP=4).
__global__ void agg_kernel(int n, int mode,
                           const float* __restrict__ bias,
                           const float* __restrict__ gamma,
                           const float* __restrict__ beta,
                           const float* __restrict__ mean,
                           const float* __restrict__ var) {
    int node = blockIdx.x * (blockDim.x >> 5) + (threadIdx.x >> 5);
    if (node >= n) return;
    int l = threadIdx.x & 31;

    float d = g_dinv[node];

    float4 a0 = ldh4(g_hh + (size_t)node * 64 + 2 * l);
    float d2 = d * d;
    a0.x *= d2; a0.y *= d2; a0.z *= d2; a0.w *= d2;
    float4 a1 = make_float4(0.f, 0.f, 0.f, 0.f);
    float4 a2 = make_float4(0.f, 0.f, 0.f, 0.f);
    float4 a3 = make_float4(0.f, 0.f, 0.f, 0.f);

    int s = g_rowptr[node], e2 = g_rowptr[node + 1];
    for (int base = s; base < e2; base += 32) {
        int idx = base + l;
        int r = (idx < e2) ? g_src[idx] : 0;
        float dr = (idx < e2) ? g_dinv[r] * d : 0.f;
        int m = e2 - base; if (m > 32) m = 32;
        int j = 0;
        for (; j + 4 <= m; j += 4) {
            int r0 = __shfl_sync(0xffffffffu, r, j);
            int r1 = __shfl_sync(0xffffffffu, r, j + 1);
            int r2 = __shfl_sync(0xffffffffu, r, j + 2);
            int r3 = __shfl_sync(0xffffffffu, r, j + 3);
            float n0 = __shfl_sync(0xffffffffu, dr, j);
            float n1 = __shfl_sync(0xffffffffu, dr, j + 1);
            float n2 = __shfl_sync(0xffffffffu, dr, j + 2);
            float n3 = __shfl_sync(0xffffffffu, dr, j + 3);
            float4 v0 = ldh4(g_hh + (size_t)r0 * 64 + 2 * l);
            float4 v1 = ldh4(g_hh + (size_t)r1 * 64 + 2 * l);
            float4 v2 = ldh4(g_hh + (size_t)r2 * 64 + 2 * l);
            float4 v3 = ldh4(g_hh + (size_t)r3 * 64 + 2 * l);
            a0.x += v0.x * n0; a0.y += v0.y * n0; a0.z += v0.z * n0; a0.w += v0.w * n0;
            a1.x += v1.x * n1; a1.y += v1.y * n1; a1.z += v1.z * n1; a1.w += v1.w * n1;
            a2.x += v2.x * n2; a2.y += v2.y * n2; a2.z += v2.z * n2; a2.w += v2.w * n2;
            a3.x += v3.x * n3; a3.y += v3.y * n3; a3.z += v3.z * n3; a3.w += v3.w * n3;
        }
        for (; j < m; j++) {
            int r0 = __shfl_sync(0xffffffffu, r, j);
            float n0 = __shfl_sync(0xffffffffu, dr, j);
            float4 v0 = ldh4(g_hh + (size_t)r0 * 64 + 2 * l);
            a0.x += v0.x * n0; a0.y += v0.y * n0; a0.z += v0.z * n0; a0.w += v0.w * n0;
        }
    }
    a0.x += a1.x + a2.x + a3.x;
    a0.y += a1.y + a2.y + a3.y;
    a0.z += a1.z + a2.z + a3.z;
    a0.w += a1.w + a2.w + a3.w;

    int c0 = 4 * l;
    float outv[4] = {a0.x, a0.y, a0.z, a0.w};
    if (mode == 1) {
#pragma unroll
        for (int m = 0; m < 4; m++) {
            int c = c0 + m;
            float v = outv[m] + bias[c];
            float sc = gamma[c] * rsqrtf(var[c] + 1e-5f);
            v = (v - mean[c]) * sc + beta[c];
            outv[m] = fmaxf(v, 0.f);
        }
    } else {
#pragma unroll
        for (int m = 0; m < 4; m++) outv[m] += bias[c0 + m];
    }
    *(float4*)(g_agg + (size_t)node * F + c0) =
        make_float4(outv[0], outv[1], outv[2], outv[3]);
}

// ---------------- launch ------------------------------------------------------
extern "C" void kernel_launch(void* const* d_in, const int* in_sizes, int n_in,
                              void* d_out, int out_size) {
    const float* x     = (const float*)d_in[0];
    const void*  eidx  = d_in[1];
    const float* w1    = (const float*)d_in[2];
    const float* b1    = (const float*)d_in[3];
    const float* w2    = (const float*)d_in[4];
    const float* b2    = (const float*)d_in[5];
    const float* gamma = (const float*)d_in[6];
    const float* beta  = (const float*)d_in[7];
    const float* mean  = (const float*)d_in[8];
    const float* var   = (const float*)d_in[9];
    const float* cls_w = (const float*)d_in[10];
    const float* cls_b = (const float*)d_in[11];
    const float* sim_w = (const float*)d_in[12];
    const float* sim_b = (const float*)d_in[13];
    const float* hom_w = (const float*)d_in[14];
    const float* hom_b = (const float*)d_in[15];
    const float* ent_w = (const float*)d_in[16];
    const float* ent_b = (const float*)d_in[17];

    int N = in_sizes[0] / F;
    long long E = (long long)in_sizes[1] / 2;
    float* out = (float*)d_out;

    float* p_agg = nullptr;
    uint2* p_bw = nullptr;
    cudaGetSymbolAddress((void**)&p_agg, g_agg);
    cudaGetSymbolAddress((void**)&p_bw, g_bw);

    size_t smemT = 8192 * sizeof(unsigned);               // 32 KB (fp16 A tile)
    size_t smemH = 128 * 128 * sizeof(float);             // 64 KB (C staging)
    cudaFuncSetAttribute(tgemm_kernel, cudaFuncAttributeMaxDynamicSharedMemorySize,
                         (int)smemT);
    cudaFuncSetAttribute(head_mma_kernel, cudaFuncAttributeMaxDynamicSharedMemorySize,
                         (int)smemH);

    int tb = 256;
    int nscan = (N + SCHUNK - 1) / SCHUNK;
    int tgG = (N + 127) / 128;

    // order chosen so tgemm1 is OUR index 3 == ncu's global launch 5
    prep_w_kernel<<<32, 256>>>(w1, p_bw);                              // 0
    zdetect_kernel<<<(N + tb - 1) / tb, tb>>>((const int*)eidx, N);    // 1
    count_kernel<<<(unsigned)((E + tb - 1) / tb), tb>>>(eidx, E);      // 2
    tgemm_kernel<<<tgG, 512, smemT>>>(x, N);                           // 3 <- ncu
    scan1_kernel<<<nscan, SCHUNK>>>(N);                                // 4
    scan3_kernel<<<nscan, SCHUNK>>>(N, nscan);                         // 5
    fill_kernel<<<(unsigned)((E + tb - 1) / tb), tb>>>(eidx, E);       // 6
    agg_kernel<<<(N + 7) / 8, tb>>>(N, 1, b1, gamma, beta, mean, var); // 7

    // layer 2
    prep_w_kernel<<<32, 256>>>(w2, p_bw);
    tgemm_kernel<<<tgG, 512, smemT>>>(p_agg, N);
    agg_kernel<<<(N + 7) / 8, tb>>>(N, 2, b2, nullptr, nullptr, nullptr, nullptr);

    // heads (mma + fused finisher)
    prep_head_kernel<<<32, 256>>>(cls_w, cls_b, sim_w, sim_b,
                                  hom_w, hom_b, ent_w, ent_b);
    head_mma_kernel<<<tgG, 512, smemH>>>(p_agg, out, N);
}

// round 17
// speedup vs baseline: 1.3648x; 1.0369x over previous
#include <cuda_runtime.h>
#include <cuda_fp16.h>
#include <math.h>
#include <stdint.h>

#define NMAX 100000
#define EMAX 1600000
#define F 128
#define HEADP 108
#define SCHUNK 512

// ---------------- scratch (static device globals; no allocation allowed) ---
__device__ __half2 g_hh[(size_t)NMAX * 64];   // GEMM output (fp16) / gather src
__device__ __half2 g_ah[(size_t)NMAX * 64];   // agg output (fp16 rows)
__device__ float g_dinv[NMAX];
__device__ int   g_deg[NMAX];
__device__ int   g_rowptr[NMAX + 1];
__device__ int   g_fill[NMAX];
__device__ int   g_src[EMAX];                 // CSR (by destination) source ids
__device__ int   g_bsum[256];
__device__ float g_hb[HEADP];
__device__ int   g_is64;
// W fragment images (plain fp16): [8 k16-steps][16 ntiles][32 lanes][2 regs]
__device__ uint2 g_bw[4096];                  // mainline layer weights (32KB)
__device__ uint2 g_bw2[4096];                 // packed head weights

#define MMA_F16(cc, a0, a1, a2, a3, b0, b1)                                    \
    asm volatile(                                                              \
        "mma.sync.aligned.m16n8k16.row.col.f32.f16.f16.f32 "                   \
        "{%0,%1,%2,%3},{%4,%5,%6,%7},{%8,%9},{%0,%1,%2,%3};"                   \
        : "+f"((cc)[0]), "+f"((cc)[1]), "+f"((cc)[2]), "+f"((cc)[3])           \
        : "r"(a0), "r"(a1), "r"(a2), "r"(a3), "r"(b0), "r"(b1))

// load 4 consecutive h cols (2 half2) and widen to float4
__device__ __forceinline__ float4 ldh4(const __half2* p) {
    uint2 u = __ldg((const uint2*)p);
    __half2 h0 = *(__half2*)&u.x;
    __half2 h1 = *(__half2*)&u.y;
    float2 f0 = __half22float2(h0);
    float2 f1 = __half22float2(h1);
    return make_float4(f0.x, f0.y, f1.x, f1.y);
}

__device__ __forceinline__ unsigned h2pack(float v0, float v1) {
    __half2 h = __floats2half2_rn(v0, v1);
    return *(unsigned*)&h;
}

// ---------------- detect dtype + zero degrees (fused) ----------------------
__global__ void zdetect_kernel(const int* __restrict__ e, int n) {
    int i = blockIdx.x * blockDim.x + threadIdx.x;
    if (i < n) g_deg[i] = 0;
    if (blockIdx.x == 0 && threadIdx.x < 32) {
        int l = threadIdx.x;
        int bad = 0;
        for (int j = l; j < 256; j += 32)
            if (e[2 * j + 1] != 0) bad = 1;
        unsigned b = __ballot_sync(0xffffffffu, bad);
        if (l == 0) g_is64 = (b == 0) ? 1 : 0;
    }
}

__device__ __forceinline__ int ldidx(const void* p, long long i, int is64) {
    return is64 ? (int)((const long long*)p)[i] : ((const int*)p)[i];
}

// ---------------- count degrees (direct edge_index read) --------------------
__global__ void count_kernel(const void* __restrict__ eidx, long long E) {
    long long t = (long long)blockIdx.x * blockDim.x + threadIdx.x;
    if (t >= E) return;
    atomicAdd(&g_deg[ldidx(eidx, E + t, g_is64)], 1);
}

// ---------------- hierarchical scan (2 stages) ------------------------------
__global__ void scan1_kernel(int n) {
    __shared__ int sh[SCHUNK];
    int t = threadIdx.x;
    int i = blockIdx.x * SCHUNK + t;
    sh[t] = (i < n) ? g_deg[i] : 0;
    __syncthreads();
#pragma unroll
    for (int off = SCHUNK / 2; off; off >>= 1) {
        if (t < off) sh[t] += sh[t + off];
        __syncthreads();
    }
    if (t == 0) g_bsum[blockIdx.x] = sh[0];
}

__global__ void scan3_kernel(int n, int nb) {
    __shared__ int bs[256];
    __shared__ int sh[SCHUNK];
    int t = threadIdx.x;
    if (t < 256) bs[t] = (t < nb) ? g_bsum[t] : 0;
    __syncthreads();
#pragma unroll
    for (int off = 1; off < 256; off <<= 1) {
        int u = (t < 256 && t >= off) ? bs[t - off] : 0;
        __syncthreads();
        if (t < 256) bs[t] += u;
        __syncthreads();
    }
    int boff = (blockIdx.x == 0) ? 0 : bs[blockIdx.x - 1];
    if (blockIdx.x == 0 && t == 0) g_rowptr[n] = bs[nb - 1];

    int i = blockIdx.x * SCHUNK + t;
    int d = (i < n) ? g_deg[i] : 0;
    sh[t] = d;
    __syncthreads();
#pragma unroll
    for (int off = 1; off < SCHUNK; off <<= 1) {
        int u = (t >= off) ? sh[t - off] : 0;
        __syncthreads();
        sh[t] += u;
        __syncthreads();
    }
    if (i < n) {
        int pre = boff + sh[t] - d;
        g_rowptr[i] = pre;
        g_fill[i]   = pre;
        g_dinv[i]   = rsqrtf((float)(d + 1));  // +1 self-loop
    }
}

__global__ void fill_kernel(const void* __restrict__ eidx, long long E) {
    long long e = (long long)blockIdx.x * blockDim.x + threadIdx.x;
    if (e >= E) return;
    int is64 = g_is64;
    int r = ldidx(eidx, e, is64);
    int c = ldidx(eidx, E + e, is64);
    int pos = atomicAdd(&g_fill[c], 1);
    g_src[pos] = r;
}

// ---------------- W prep: plain fp16 m16n8k16 B-fragment image --------------
__global__ void prep_w_kernel(const float* __restrict__ W, uint2* __restrict__ img) {
    int p = blockIdx.x * blockDim.x + threadIdx.x;
    if (p >= 8192) return;
    int kp = p >> 7, n = p & 127;
    int k = 2 * kp;
    float v0 = W[k * 128 + n];
    float v1 = W[(k + 1) * 128 + n];
    int s = k >> 4, kw = k & 15;
    int reg = kw >> 3, t = (kw & 7) >> 1;
    int tile = s * 16 + (n >> 3);
    ((unsigned*)img)[(tile * 32 + (n & 7) * 4 + t) * 2 + reg] = h2pack(v0, v1);
}

// same, gathering packed head weights (cls|sim|hom|ent, zero-padded to 128)
__global__ void prep_head_kernel(const float* __restrict__ cls_w,
                                 const float* __restrict__ cls_b,
                                 const float* __restrict__ sim_w,
                                 const float* __restrict__ sim_b,
                                 const float* __restrict__ hom_w,
                                 const float* __restrict__ hom_b,
                                 const float* __restrict__ ent_w,
                                 const float* __restrict__ ent_b) {
    int p = blockIdx.x * blockDim.x + threadIdx.x;
    if (p < HEADP) {
        float v = 0.f;
        if (p < 64)        v = cls_b[p];
        else if (p < 104)  v = sim_b[p - 64];
        else if (p == 104) v = hom_b[0];
        else if (p == 105) v = ent_b[0];
        g_hb[p] = v;
    }
    if (p >= 8192) return;
    int kp = p >> 7, n = p & 127;
    int k = 2 * kp;
    float v0 = 0.f, v1 = 0.f;
    if (n < 64)        { v0 = cls_w[k * 64 + n];        v1 = cls_w[(k + 1) * 64 + n]; }
    else if (n < 104)  { v0 = sim_w[k * 40 + n - 64];   v1 = sim_w[(k + 1) * 40 + n - 64]; }
    else if (n == 104) { v0 = hom_w[k];                 v1 = hom_w[k + 1]; }
    else if (n == 105) { v0 = ent_w[k];                 v1 = ent_w[k + 1]; }
    int s = k >> 4, kw = k & 15;
    int reg = kw >> 3, t = (kw & 7) >> 1;
    int tile = s * 16 + (n >> 3);
    ((unsigned*)g_bw2)[(tile * 32 + (n & 7) * 4 + t) * 2 + reg] = h2pack(v0, v1);
}

// ---------------- staging variants ------------------------------------------
// As layout: [mtile(8)][s(8)][lane(32)][reg(4)] unsigned (32KB).
__device__ __forceinline__ void stage_fp32(const float* __restrict__ A,
                                           unsigned* As, long long row0, int M,
                                           int tid) {
    for (int idx = tid; idx < 4096; idx += 512) {
        int r = idx >> 5, q = idx & 31;
        long long gr = row0 + r;
        float4 v = make_float4(0.f, 0.f, 0.f, 0.f);
        if (gr < M) v = __ldg((const float4*)(A + gr * F) + q);
        int mtile = r >> 4, ri = r & 15;
        int g = ri & 7, rowhalf = ri >> 3;
        int s = q >> 2;
        int reg = ((q >> 1) & 1) * 2 + rowhalf;
        int t = (q & 1) * 2;
        unsigned* base = As + ((mtile * 8 + s) * 32) * 4;
        base[(g * 4 + t) * 4 + reg]     = h2pack(v.x, v.y);
        base[(g * 4 + t + 1) * 4 + reg] = h2pack(v.z, v.w);
    }
    __syncthreads();
}

// fp16 rows: each uint4 = 4 A-fragment words, zero conversion ALU
__device__ __forceinline__ void stage_fp16(const __half2* __restrict__ AH,
                                           unsigned* As, long long row0, int M,
                                           int tid) {
    for (int idx = tid; idx < 2048; idx += 512) {
        int r = idx >> 4, q4 = idx & 15;
        long long gr = row0 + r;
        uint4 u = make_uint4(0u, 0u, 0u, 0u);
        if (gr < M) u = __ldg((const uint4*)(AH + gr * 64) + q4);
        int mtile = r >> 4, ri = r & 15;
        int g = ri & 7, rowhalf = ri >> 3;
        int s = q4 >> 1;
        int reg = (q4 & 1) * 2 + rowhalf;
        unsigned* base = As + ((mtile * 8 + s) * 32) * 4;
        base[(g * 4 + 0) * 4 + reg] = u.x;
        base[(g * 4 + 1) * 4 + reg] = u.y;
        base[(g * 4 + 2) * 4 + reg] = u.z;
        base[(g * 4 + 3) * 4 + reg] = u.w;
    }
    __syncthreads();
}

// ---------------- fully-fp16 mma compute (512 threads) -----------------------
// 16 warps (4M x 4N), warp tile 32x32, 8 k16-steps.
__device__ __forceinline__ void mma_compute(const uint2* __restrict__ bimg,
                                            const unsigned* As,
                                            int lane, int wm, int wn,
                                            float c[2][4][4]) {
#pragma unroll
    for (int s = 0; s < 8; s++) {
        uint2 b[4];
#pragma unroll
        for (int nf = 0; nf < 4; nf++)
            b[nf] = __ldg(&bimg[(s * 16 + wn * 4 + nf) * 32 + lane]);
#pragma unroll
        for (int mf = 0; mf < 2; mf++) {
            int mtile = wm * 2 + mf;
            uint4 a = *(const uint4*)&As[(((mtile * 8 + s) * 32) + lane) * 4];
#pragma unroll
            for (int nf = 0; nf < 4; nf++)
                MMA_F16(c[mf][nf], a.x, a.y, a.z, a.w, b[nf].x, b[nf].y);
        }
    }
}

__device__ __forceinline__ void gemm_epilogue(float c[2][4][4], long long row0,
                                              int M, int lane, int wm, int wn) {
#pragma unroll
    for (int mf = 0; mf < 2; mf++) {
        long long r0 = row0 + wm * 32 + mf * 16 + (lane >> 2);
#pragma unroll
        for (int nf = 0; nf < 4; nf++) {
            int ch = wn * 16 + nf * 4 + (lane & 3);   // half2 column index
            if (r0 < M)
                g_hh[r0 * 64 + ch] = __floats2half2_rn(c[mf][nf][0], c[mf][nf][1]);
            if (r0 + 8 < M)
                g_hh[(r0 + 8) * 64 + ch] = __floats2half2_rn(c[mf][nf][2], c[mf][nf][3]);
        }
    }
}

// ---------------- layer-1 GEMM (fp32 in): h = x @ W1 -------------------------
__global__ __launch_bounds__(512, 2)
void tgemm_kernel(const float* __restrict__ A, int M) {
    extern __shared__ unsigned smu[];
    int tid = threadIdx.x, lane = tid & 31, wid = tid >> 5;
    int wm = wid >> 2, wn = wid & 3;
    long long row0 = (long long)blockIdx.x * 128;

    float c[2][4][4];
#pragma unroll
    for (int a = 0; a < 2; a++)
#pragma unroll
        for (int b = 0; b < 4; b++)
#pragma unroll
            for (int d = 0; d < 4; d++) c[a][b][d] = 0.f;

    stage_fp32(A, smu, row0, M, tid);
    mma_compute(g_bw, smu, lane, wm, wn, c);
    gemm_epilogue(c, row0, M, lane, wm, wn);
}

// ---------------- layer-2 GEMM (fp16 in): h = ah @ W2 ------------------------
__global__ __launch_bounds__(512, 2)
void tgemm2_kernel(int M) {
    extern __shared__ unsigned smu[];
    int tid = threadIdx.x, lane = tid & 31, wid = tid >> 5;
    int wm = wid >> 2, wn = wid & 3;
    long long row0 = (long long)blockIdx.x * 128;

    float c[2][4][4];
#pragma unroll
    for (int a = 0; a < 2; a++)
#pragma unroll
        for (int b = 0; b < 4; b++)
#pragma unroll
            for (int d = 0; d < 4; d++) c[a][b][d] = 0.f;

    stage_fp16(g_ah, smu, row0, M, tid);
    mma_compute(g_bw, smu, lane, wm, wn, c);
    gemm_epilogue(c, row0, M, lane, wm, wn);
}

// ---------------- head GEMM (fp16 in) + fused finisher -----------------------
__global__ __launch_bounds__(512, 2)
void head_mma_kernel(float* __restrict__ out, int M) {
    extern __shared__ unsigned smu[];
    unsigned* As = smu;            // 32KB of the 64KB allocation
    float* Cs = (float*)smu;       // reused after mainloop: 128 x 128 floats
    __shared__ float sbias[128];

    int tid = threadIdx.x, lane = tid & 31, wid = tid >> 5;
    int wm = wid >> 2, wn = wid & 3;
    long long row0 = (long long)blockIdx.x * 128;

    if (tid < 128) sbias[tid] = (tid < HEADP) ? g_hb[tid] : 0.f;

    float c[2][4][4];
#pragma unroll
    for (int a = 0; a < 2; a++)
#pragma unroll
        for (int b = 0; b < 4; b++)
#pragma unroll
            for (int d = 0; d < 4; d++) c[a][b][d] = 0.f;

    stage_fp16(g_ah, As, row0, M, tid);
    mma_compute(g_bw2, As, lane, wm, wn, c);
    __syncthreads();   // all warps done reading As before Cs overwrite

    // stage C into SMEM (stride 128 -> finisher reads are conflict-free)
#pragma unroll
    for (int mf = 0; mf < 2; mf++) {
        int r0 = wm * 32 + mf * 16 + (lane >> 2);
#pragma unroll
        for (int nf = 0; nf < 4; nf++) {
            int col = wn * 32 + nf * 8 + 2 * (lane & 3);
            *(float2*)&Cs[r0 * 128 + col] = make_float2(c[mf][nf][0], c[mf][nf][1]);
            *(float2*)&Cs[(r0 + 8) * 128 + col] = make_float2(c[mf][nf][2], c[mf][nf][3]);
        }
    }
    __syncthreads();

    float* out_main = out;                     // [M,64]
    float* out_sim  = out + (size_t)M * 64;    // [M,40]
    float* out_hom  = out + (size_t)M * 104;   // [M]
    float* out_ent  = out + (size_t)M * 105;   // [M]

    for (int i = 0; i < 8; i++) {
        int row = wid * 8 + i;
        long long gr = row0 + row;
        if (gr >= M) break;
        const float* g = Cs + row * 128;

        // log_softmax over cols [0,64)
        float a = g[lane] + sbias[lane];
        float b = g[32 + lane] + sbias[32 + lane];
        float m1 = fmaxf(a, b);
#pragma unroll
        for (int o = 16; o; o >>= 1)
            m1 = fmaxf(m1, __shfl_xor_sync(0xffffffffu, m1, o));
        float s = expf(a - m1) + expf(b - m1);
#pragma unroll
        for (int o = 16; o; o >>= 1) s += __shfl_xor_sync(0xffffffffu, s, o);
        float ls = m1 + logf(s);
        out_main[gr * 64 + lane]      = a - ls;
        out_main[gr * 64 + 32 + lane] = b - ls;

        // softmax over cols [64,104)
        float u = g[64 + lane] + sbias[64 + lane];
        float v2 = (lane < 8) ? g[96 + lane] + sbias[96 + lane] : -3.0e38f;
        float m2 = fmaxf(u, v2);
#pragma unroll
        for (int o = 16; o; o >>= 1)
            m2 = fmaxf(m2, __shfl_xor_sync(0xffffffffu, m2, o));
        float e1 = expf(u - m2);
        float e2 = (lane < 8) ? expf(v2 - m2) : 0.f;
        float s2 = e1 + e2;
#pragma unroll
        for (int o = 16; o; o >>= 1) s2 += __shfl_xor_sync(0xffffffffu, s2, o);
        float inv = 1.f / s2;
        out_sim[gr * 40 + lane] = e1 * inv;
        if (lane < 8) out_sim[gr * 40 + 32 + lane] = e2 * inv;

        // sigmoids
        if (lane == 0) out_hom[gr] = 1.f / (1.f + expf(-(g[104] + sbias[104])));
        if (lane == 1) out_ent[gr] = 1.f / (1.f + expf(-(g[105] + sbias[105])));
    }
}

// ---------------- CSR gather aggregation (fp16 src, fp16 out, MLP=8) --------
// mode 1: +b1, BN(eval), ReLU.   mode 2: +b2.
__global__ void agg_kernel(int n, int mode,
                           const float* __restrict__ bias,
                           const float* __restrict__ gamma,
                           const float* __restrict__ beta,
                           const float* __restrict__ mean,
                           const float* __restrict__ var) {
    int node = blockIdx.x * (blockDim.x >> 5) + (threadIdx.x >> 5);
    if (node >= n) return;
    int l = threadIdx.x & 31;

    float d = g_dinv[node];

    float4 acc[4];
    acc[0] = ldh4(g_hh + (size_t)node * 64 + 2 * l);
    float d2 = d * d;
    acc[0].x *= d2; acc[0].y *= d2; acc[0].z *= d2; acc[0].w *= d2;
    acc[1] = make_float4(0.f, 0.f, 0.f, 0.f);
    acc[2] = make_float4(0.f, 0.f, 0.f, 0.f);
    acc[3] = make_float4(0.f, 0.f, 0.f, 0.f);

    int s = g_rowptr[node], e2 = g_rowptr[node + 1];
    for (int base = s; base < e2; base += 32) {
        int idx = base + l;
        int r = (idx < e2) ? g_src[idx] : 0;
        float dr = (idx < e2) ? g_dinv[r] * d : 0.f;
        int m = e2 - base; if (m > 32) m = 32;
        int j = 0;
        for (; j + 8 <= m; j += 8) {
            int rr[8]; float nn[8];
#pragma unroll
            for (int u = 0; u < 8; u++) {
                rr[u] = __shfl_sync(0xffffffffu, r, j + u);
                nn[u] = __shfl_sync(0xffffffffu, dr, j + u);
            }
            float4 vv[8];
#pragma unroll
            for (int u = 0; u < 8; u++)
                vv[u] = ldh4(g_hh + (size_t)rr[u] * 64 + 2 * l);
#pragma unroll
            for (int u = 0; u < 8; u++) {
                float4* A4 = &acc[u & 3];
                A4->x += vv[u].x * nn[u]; A4->y += vv[u].y * nn[u];
                A4->z += vv[u].z * nn[u]; A4->w += vv[u].w * nn[u];
            }
        }
        for (; j + 4 <= m; j += 4) {
            int rr[4]; float nn[4];
#pragma unroll
            for (int u = 0; u < 4; u++) {
                rr[u] = __shfl_sync(0xffffffffu, r, j + u);
                nn[u] = __shfl_sync(0xffffffffu, dr, j + u);
            }
            float4 vv[4];
#pragma unroll
            for (int u = 0; u < 4; u++)
                vv[u] = ldh4(g_hh + (size_t)rr[u] * 64 + 2 * l);
#pragma unroll
            for (int u = 0; u < 4; u++) {
                float4* A4 = &acc[u];
                A4->x += vv[u].x * nn[u]; A4->y += vv[u].y * nn[u];
                A4->z += vv[u].z * nn[u]; A4->w += vv[u].w * nn[u];
            }
        }
        for (; j < m; j++) {
            int r0 = __shfl_sync(0xffffffffu, r, j);
            float n0 = __shfl_sync(0xffffffffu, dr, j);
            float4 v0 = ldh4(g_hh + (size_t)r0 * 64 + 2 * l);
            acc[0].x += v0.x * n0; acc[0].y += v0.y * n0;
            acc[0].z += v0.z * n0; acc[0].w += v0.w * n0;
        }
    }
    float outv[4];
    outv[0] = acc[0].x + acc[1].x + acc[2].x + acc[3].x;
    outv[1] = acc[0].y + acc[1].y + acc[2].y + acc[3].y;
    outv[2] = acc[0].z + acc[1].z + acc[2].z + acc[3].z;
    outv[3] = acc[0].w + acc[1].w + acc[2].w + acc[3].w;

    int c0 = 4 * l;
    if (mode == 1) {
#pragma unroll
        for (int m = 0; m < 4; m++) {
            int c = c0 + m;
            float v = outv[m] + bias[c];
            float sc = gamma[c] * rsqrtf(var[c] + 1e-5f);
            v = (v - mean[c]) * sc + beta[c];
            outv[m] = fmaxf(v, 0.f);
        }
    } else {
#pragma unroll
        for (int m = 0; m < 4; m++) outv[m] += bias[c0 + m];
    }
    // fp16 row output (same layout as g_hh; consumed by stage_fp16)
    g_ah[(size_t)node * 64 + 2 * l]     = __floats2half2_rn(outv[0], outv[1]);
    g_ah[(size_t)node * 64 + 2 * l + 1] = __floats2half2_rn(outv[2], outv[3]);
}

// ---------------- launch ------------------------------------------------------
extern "C" void kernel_launch(void* const* d_in, const int* in_sizes, int n_in,
                              void* d_out, int out_size) {
    const float* x     = (const float*)d_in[0];
    const void*  eidx  = d_in[1];
    const float* w1    = (const float*)d_in[2];
    const float* b1    = (const float*)d_in[3];
    const float* w2    = (const float*)d_in[4];
    const float* b2    = (const float*)d_in[5];
    const float* gamma = (const float*)d_in[6];
    const float* beta  = (const float*)d_in[7];
    const float* mean  = (const float*)d_in[8];
    const float* var   = (const float*)d_in[9];
    const float* cls_w = (const float*)d_in[10];
    const float* cls_b = (const float*)d_in[11];
    const float* sim_w = (const float*)d_in[12];
    const float* sim_b = (const float*)d_in[13];
    const float* hom_w = (const float*)d_in[14];
    const float* hom_b = (const float*)d_in[15];
    const float* ent_w = (const float*)d_in[16];
    const float* ent_b = (const float*)d_in[17];

    int N = in_sizes[0] / F;
    long long E = (long long)in_sizes[1] / 2;
    float* out = (float*)d_out;

    uint2* p_bw = nullptr;
    cudaGetSymbolAddress((void**)&p_bw, g_bw);

    size_t smemT = 8192 * sizeof(unsigned);               // 32 KB (fp16 A tile)
    size_t smemH = 128 * 128 * sizeof(float);             // 64 KB (C staging)
    cudaFuncSetAttribute(tgemm_kernel, cudaFuncAttributeMaxDynamicSharedMemorySize,
                         (int)smemT);
    cudaFuncSetAttribute(tgemm2_kernel, cudaFuncAttributeMaxDynamicSharedMemorySize,
                         (int)smemT);
    cudaFuncSetAttribute(head_mma_kernel, cudaFuncAttributeMaxDynamicSharedMemorySize,
                         (int)smemH);

    int tb = 256;
    int nscan = (N + SCHUNK - 1) / SCHUNK;
    int tgG = (N + 127) / 128;

    // order chosen so tgemm1 is OUR index 3 == ncu's global launch 5
    prep_w_kernel<<<32, 256>>>(w1, p_bw);                              // 0
    zdetect_kernel<<<(N + tb - 1) / tb, tb>>>((const int*)eidx, N);    // 1
    count_kernel<<<(unsigned)((E + tb - 1) / tb), tb>>>(eidx, E);      // 2
    tgemm_kernel<<<tgG, 512, smemT>>>(x, N);                           // 3 <- ncu
    scan1_kernel<<<nscan, SCHUNK>>>(N);                                // 4
    scan3_kernel<<<nscan, SCHUNK>>>(N, nscan);                         // 5
    fill_kernel<<<(unsigned)((E + tb - 1) / tb), tb>>>(eidx, E);       // 6
    agg_kernel<<<(N + 7) / 8, tb>>>(N, 1, b1, gamma, beta, mean, var); // 7

    // layer 2
    prep_w_kernel<<<32, 256>>>(w2, p_bw);
    tgemm2_kernel<<<tgG, 512, smemT>>>(N);
    agg_kernel<<<(N + 7) / 8, tb>>>(N, 2, b2, nullptr, nullptr, nullptr, nullptr);

    // heads (mma + fused finisher)
    prep_head_kernel<<<32, 256>>>(cls_w, cls_b, sim_w, sim_b,
                                  hom_w, hom_b, ent_w, ent_b);
    head_mma_kernel<<<tgG, 512, smemH>>>(out, N);
}